// round 1
// baseline (speedup 1.0000x reference)
#include <cuda_runtime.h>
#include <math_constants.h>

// Problem constants (fixed by the dataset)
#define BB 2
#define LL 2048
#define DD 1024
#define HH 16
#define DH 64
#define MM (BB*LL)   // 4096 rows

// Scratch (allocation-free rule: __device__ globals)
__device__ float g_q[MM*DD];
__device__ float g_k[MM*DD];
__device__ float g_v[MM*DD];
__device__ float g_y[MM*DD];

// ---------------------------------------------------------------------------
// Tiled SGEMM: C[M=4096, N=1024] = scale * A[4096,1024] @ W[1024,1024]
// BM=BN=128, BK=8, 256 threads, 8x8 per thread.
// ---------------------------------------------------------------------------
__global__ __launch_bounds__(256) void sgemm128(const float* __restrict__ A,
                                                const float* __restrict__ W,
                                                float* __restrict__ C,
                                                float scale) {
    __shared__ float As[8][128];
    __shared__ float Bs[8][128];

    const int bx = blockIdx.x;      // N tile (0..7)
    const int by = blockIdx.y;      // M tile (0..31)
    const int tid = threadIdx.x;
    const int tx = tid & 15;        // 0..15 -> 8 cols each
    const int ty = tid >> 4;        // 0..15 -> 8 rows each

    const float* Ab = A + (size_t)by * 128 * DD;
    const float* Wb = W + bx * 128;

    float acc[8][8];
    #pragma unroll
    for (int i = 0; i < 8; i++)
        #pragma unroll
        for (int j = 0; j < 8; j++) acc[i][j] = 0.f;

    for (int k0 = 0; k0 < DD; k0 += 8) {
        // Load A tile 128x8 -> As[k][m]
        {
            int m  = tid >> 1;            // 0..127
            int h4 = (tid & 1) * 4;       // 0 or 4
            float4 v = *(const float4*)(Ab + m * DD + k0 + h4);
            As[h4 + 0][m] = v.x;
            As[h4 + 1][m] = v.y;
            As[h4 + 2][m] = v.z;
            As[h4 + 3][m] = v.w;
        }
        // Load W tile 8x128 -> Bs[k][n] (coalesced rows)
        #pragma unroll
        for (int i = tid; i < 8 * 128; i += 256) {
            int kk = i >> 7, n = i & 127;
            Bs[kk][n] = Wb[(size_t)(k0 + kk) * DD + n];
        }
        __syncthreads();

        #pragma unroll
        for (int kk = 0; kk < 8; kk++) {
            float a[8], b[8];
            #pragma unroll
            for (int i = 0; i < 8; i++) a[i] = As[kk][ty * 8 + i];
            #pragma unroll
            for (int j = 0; j < 8; j++) b[j] = Bs[kk][tx * 8 + j];
            #pragma unroll
            for (int i = 0; i < 8; i++)
                #pragma unroll
                for (int j = 0; j < 8; j++) acc[i][j] += a[i] * b[j];
        }
        __syncthreads();
    }

    #pragma unroll
    for (int i = 0; i < 8; i++) {
        float* crow = C + (size_t)(by * 128 + ty * 8 + i) * DD + bx * 128 + tx * 8;
        #pragma unroll
        for (int j = 0; j < 8; j++) crow[j] = acc[i][j] * scale;
    }
}

// ---------------------------------------------------------------------------
// RoPE on q and k (in place). One thread per (row, pair).
// pair index within head: hc in [0,32); inv_freq = 10000^(-2*hc/64)
// ---------------------------------------------------------------------------
__global__ __launch_bounds__(256) void rope_kernel(float* __restrict__ q,
                                                   float* __restrict__ k) {
    int idx = blockIdx.x * blockDim.x + threadIdx.x;   // over MM * (DD/2)
    if (idx >= MM * (DD / 2)) return;
    int row = idx / (DD / 2);
    int pc  = idx % (DD / 2);
    int pos = row & (LL - 1);          // position within sequence
    int hc  = pc & (DH / 2 - 1);       // pair index within head

    // inv_freq = 2^( -hc * (2/64) * log2(10000) )
    float inv = exp2f(-(float)hc * 0.41524101186092029f);
    float ang = (float)pos * inv;
    float s, c;
    __sincosf(ang, &s, &c);            // fast path first; fall back if precision issue
    // use accurate versions (compiler keeps them separate from fast intrinsics)
    s = sinf(ang); c = cosf(ang);

    float2* qp = (float2*)q;
    float2* kp = (float2*)k;
    float2 vq = qp[idx];
    qp[idx] = make_float2(vq.x * c - vq.y * s, vq.y * c + vq.x * s);
    float2 vk = kp[idx];
    kp[idx] = make_float2(vk.x * c - vk.y * s, vk.y * c + vk.x * s);
}

// ---------------------------------------------------------------------------
// Flash-style causal attention.
// Grid: (L/128 query tiles, B*H). Block: 128 threads, 1 thread = 1 query row.
// K/V tiles of 64 rows staged in smem; online softmax with lazy rescale.
// ---------------------------------------------------------------------------
__global__ __launch_bounds__(128) void flash_attn() {
    __shared__ float Ks[64][64];
    __shared__ float Vs[64][64];

    const int qt  = blockIdx.x;        // 0..15
    const int bh  = blockIdx.y;        // 0..31
    const int b   = bh >> 4;
    const int h   = bh & 15;
    const int tid = threadIdx.x;
    const int r   = qt * 128 + tid;    // query position 0..2047

    const float* qptr = g_q + ((size_t)(b * LL + r)) * DD + h * DH;
    float q[DH], o[DH];
    #pragma unroll
    for (int d = 0; d < DH; d++) { q[d] = qptr[d]; o[d] = 0.f; }

    float mmax = -CUDART_INF_F;
    float lsum = 0.f;

    const int kt_max = (qt * 128 + 127) >> 6;    // inclusive
    for (int kt = 0; kt <= kt_max; kt++) {
        const float* kbase = g_k + ((size_t)(b * LL + kt * 64)) * DD + h * DH;
        const float* vbase = g_v + ((size_t)(b * LL + kt * 64)) * DD + h * DH;
        __syncthreads();
        #pragma unroll
        for (int i = tid; i < 64 * 16; i += 128) {
            int row = i >> 4, c4 = i & 15;
            ((float4*)Ks[row])[c4] = ((const float4*)(kbase + (size_t)row * DD))[c4];
            ((float4*)Vs[row])[c4] = ((const float4*)(vbase + (size_t)row * DD))[c4];
        }
        __syncthreads();

        const int jmax = min(63, r - kt * 64);
        for (int j = 0; j <= jmax; j++) {
            float s = 0.f;
            #pragma unroll
            for (int d = 0; d < DH; d++) s += q[d] * Ks[j][d];

            if (s > mmax) {
                float corr = __expf(mmax - s);   // first key: exp(-inf)=0, clean
                lsum *= corr;
                #pragma unroll
                for (int d = 0; d < DH; d++) o[d] *= corr;
                mmax = s;
            }
            float p = __expf(s - mmax);
            lsum += p;
            #pragma unroll
            for (int d = 0; d < DH; d++) o[d] += p * Vs[j][d];
        }
    }

    const float invl = 1.f / lsum;
    float* yptr = g_y + ((size_t)(b * LL + r)) * DD + h * DH;
    #pragma unroll
    for (int d = 0; d < DH; d++) yptr[d] = o[d] * invl;
}

// ---------------------------------------------------------------------------
extern "C" void kernel_launch(void* const* d_in, const int* in_sizes, int n_in,
                              void* d_out, int out_size) {
    const float* x  = (const float*)d_in[0];
    const float* Wq = (const float*)d_in[1];
    const float* Wk = (const float*)d_in[2];
    const float* Wv = (const float*)d_in[3];
    const float* Wo = (const float*)d_in[4];
    float* out = (float*)d_out;

    float *q, *k, *v, *y;
    cudaGetSymbolAddress((void**)&q, g_q);
    cudaGetSymbolAddress((void**)&k, g_k);
    cudaGetSymbolAddress((void**)&v, g_v);
    cudaGetSymbolAddress((void**)&y, g_y);

    dim3 ggrid(DD / 128, MM / 128);
    const float qscale = 1.0f / 32.0f;   // 1/sqrt(1024)

    sgemm128<<<ggrid, 256>>>(x, Wq, q, qscale);
    sgemm128<<<ggrid, 256>>>(x, Wk, k, 1.0f);
    sgemm128<<<ggrid, 256>>>(x, Wv, v, 1.0f);

    int npairs = MM * (DD / 2);
    rope_kernel<<<(npairs + 255) / 256, 256>>>(q, k);

    dim3 agrid(LL / 128, BB * HH);
    flash_attn<<<agrid, 128>>>();

    sgemm128<<<ggrid, 256>>>(y, Wo, out, 1.0f);
}

// round 3
// speedup vs baseline: 1.8598x; 1.8598x over previous
#include <cuda_runtime.h>
#include <math_constants.h>
#include <cstdint>

// Problem constants (fixed by the dataset)
#define BB 2
#define LL 2048
#define DD 1024
#define HH 16
#define DH 64
#define MM (BB*LL)   // 4096 rows

// GEMM tiling
#define BM 128
#define BN 128
#define BKG 16
#define NIT (DD / BKG)        // 64
#define APAD 4
#define LDA (BM + APAD)       // 132 floats: As[k][m]
#define LDB (BN + APAD)       // 132 floats: Bs[k][n]

// Scratch (allocation-free rule: __device__ globals)
__device__ float g_q[MM*DD];
__device__ float g_k[MM*DD];
__device__ float g_v[MM*DD];
__device__ float g_y[MM*DD];

// ---------------------------------------------------------------------------
__device__ __forceinline__ float tf32r(float x) {
    uint32_t u;
    asm("cvt.rna.tf32.f32 %0, %1;" : "=r"(u) : "f"(x));
    return __uint_as_float(u);
}

__device__ __forceinline__ void mma_tf32(float* d, const float* a, const float* b) {
    asm volatile(
        "mma.sync.aligned.m16n8k8.row.col.f32.tf32.tf32.f32 "
        "{%0,%1,%2,%3}, {%4,%5,%6,%7}, {%8,%9}, {%0,%1,%2,%3};\n"
        : "+f"(d[0]), "+f"(d[1]), "+f"(d[2]), "+f"(d[3])
        : "r"(__float_as_uint(a[0])), "r"(__float_as_uint(a[1])),
          "r"(__float_as_uint(a[2])), "r"(__float_as_uint(a[3])),
          "r"(__float_as_uint(b[0])), "r"(__float_as_uint(b[1])));
}

// ---------------------------------------------------------------------------
// tf32 mma.sync GEMM: C[M,1024] = scale * A[M,1024] @ W[1024,1024]
// A row-major [m][k], W row-major [k][n] (native layouts, no transpose).
// Block 128x128, BK=16, 256 threads = 8 warps (4m x 2n), warp tile 32x64.
// ---------------------------------------------------------------------------
__global__ __launch_bounds__(256) void gemm_mma(const float* __restrict__ A,
                                                const float* __restrict__ W,
                                                float* __restrict__ C,
                                                float scale) {
    __shared__ float As[2][BKG][LDA];   // [k][m], padded
    __shared__ float Bs[2][BKG][LDB];   // [k][n], padded

    const int tid  = threadIdx.x;
    const int wid  = tid >> 5;
    const int lane = tid & 31;
    const int grp  = lane >> 2;      // 0..7
    const int tig  = lane & 3;       // 0..3
    const int m0   = blockIdx.y * BM;
    const int n0   = blockIdx.x * BN;
    const int wm0  = (wid >> 1) * 32;    // warp m offset in tile
    const int wn0  = (wid & 1) * 64;     // warp n offset in tile

    float acc[2][8][4];
    #pragma unroll
    for (int mt = 0; mt < 2; mt++)
        #pragma unroll
        for (int nt = 0; nt < 8; nt++)
            #pragma unroll
            for (int r = 0; r < 4; r++) acc[mt][nt][r] = 0.f;

    // gmem load mapping:
    // A: 512 float4 per tile: f -> m = f>>2 (0..127), kq = f&3 (k quad)
    // B: 512 float4 per tile: f -> k = f>>5 (0..15), nq = f&31 (n quad)
    const int am[2] = { tid >> 2, (tid + 256) >> 2 };
    const int akq[2] = { tid & 3, tid & 3 };           // (tid+256)&3 == tid&3
    const int bk[2] = { tid >> 5, (tid + 256) >> 5 };
    const int bnq[2] = { tid & 31, tid & 31 };

    float4 ra[2], rb[2];

    auto loadT = [&](int it) {
        const int k0 = it * BKG;
        #pragma unroll
        for (int j = 0; j < 2; j++) {
            ra[j] = *(const float4*)(A + (size_t)(m0 + am[j]) * DD + k0 + akq[j] * 4);
            rb[j] = *(const float4*)(W + (size_t)(k0 + bk[j]) * DD + n0 + bnq[j] * 4);
        }
    };
    auto storeT = [&](int buf) {
        #pragma unroll
        for (int j = 0; j < 2; j++) {
            // A transposed into [k][m] with tf32 rounding
            As[buf][akq[j] * 4 + 0][am[j]] = tf32r(ra[j].x);
            As[buf][akq[j] * 4 + 1][am[j]] = tf32r(ra[j].y);
            As[buf][akq[j] * 4 + 2][am[j]] = tf32r(ra[j].z);
            As[buf][akq[j] * 4 + 3][am[j]] = tf32r(ra[j].w);
            float4 t = make_float4(tf32r(rb[j].x), tf32r(rb[j].y),
                                   tf32r(rb[j].z), tf32r(rb[j].w));
            *(float4*)&Bs[buf][bk[j]][bnq[j] * 4] = t;
        }
    };

    loadT(0);
    storeT(0);
    __syncthreads();

    for (int it = 0; it < NIT; it++) {
        const int buf = it & 1;
        if (it + 1 < NIT) loadT(it + 1);

        #pragma unroll
        for (int ks = 0; ks < 2; ks++) {
            const int kb = ks * 8;
            float a[2][4], b[8][2];
            #pragma unroll
            for (int mt = 0; mt < 2; mt++) {
                const int m = wm0 + mt * 16;
                a[mt][0] = As[buf][kb + tig    ][m + grp];
                a[mt][1] = As[buf][kb + tig    ][m + grp + 8];
                a[mt][2] = As[buf][kb + tig + 4][m + grp];
                a[mt][3] = As[buf][kb + tig + 4][m + grp + 8];
            }
            #pragma unroll
            for (int nt = 0; nt < 8; nt++) {
                const int n = wn0 + nt * 8;
                b[nt][0] = Bs[buf][kb + tig    ][n + grp];
                b[nt][1] = Bs[buf][kb + tig + 4][n + grp];
            }
            #pragma unroll
            for (int mt = 0; mt < 2; mt++)
                #pragma unroll
                for (int nt = 0; nt < 8; nt++)
                    mma_tf32(acc[mt][nt], a[mt], b[nt]);
        }

        if (it + 1 < NIT) storeT(buf ^ 1);
        __syncthreads();
    }

    // epilogue: c0:(grp, 2tig) c1:(grp, 2tig+1) c2:(grp+8, 2tig) c3:(grp+8, 2tig+1)
    #pragma unroll
    for (int mt = 0; mt < 2; mt++) {
        #pragma unroll
        for (int nt = 0; nt < 8; nt++) {
            const int m = m0 + wm0 + mt * 16 + grp;
            const int n = n0 + wn0 + nt * 8 + 2 * tig;
            float2 lo = make_float2(acc[mt][nt][0] * scale, acc[mt][nt][1] * scale);
            float2 hi = make_float2(acc[mt][nt][2] * scale, acc[mt][nt][3] * scale);
            *(float2*)(C + (size_t)m * DD + n) = lo;
            *(float2*)(C + (size_t)(m + 8) * DD + n) = hi;
        }
    }
}

// ---------------------------------------------------------------------------
// RoPE on q and k (in place). One thread per (row, pair).
// ---------------------------------------------------------------------------
__global__ __launch_bounds__(256) void rope_kernel(float* __restrict__ q,
                                                   float* __restrict__ k) {
    int idx = blockIdx.x * blockDim.x + threadIdx.x;   // over MM * (DD/2)
    if (idx >= MM * (DD / 2)) return;
    int row = idx / (DD / 2);
    int pc  = idx % (DD / 2);
    int pos = row & (LL - 1);
    int hc  = pc & (DH / 2 - 1);

    float inv = exp2f(-(float)hc * 0.41524101186092029f);  // 10000^(-2hc/64)
    float ang = (float)pos * inv;
    float s = sinf(ang), c = cosf(ang);

    float2* qp = (float2*)q;
    float2* kp = (float2*)k;
    float2 vq = qp[idx];
    qp[idx] = make_float2(vq.x * c - vq.y * s, vq.y * c + vq.x * s);
    float2 vk = kp[idx];
    kp[idx] = make_float2(vk.x * c - vk.y * s, vk.y * c + vk.x * s);
}

// ---------------------------------------------------------------------------
// Flash-style causal attention (FFMA), float4-vectorized smem reads.
// ---------------------------------------------------------------------------
__global__ __launch_bounds__(128) void flash_attn() {
    __shared__ float4 Ks[64][16];
    __shared__ float4 Vs[64][16];

    const int qt  = blockIdx.x;        // 0..15
    const int bh  = blockIdx.y;        // 0..31
    const int b   = bh >> 4;
    const int h   = bh & 15;
    const int tid = threadIdx.x;
    const int r   = qt * 128 + tid;

    const float4* qptr = (const float4*)(g_q + ((size_t)(b * LL + r)) * DD + h * DH);
    float4 q4[16], o4[16];
    #pragma unroll
    for (int d = 0; d < 16; d++) {
        q4[d] = qptr[d];
        o4[d] = make_float4(0.f, 0.f, 0.f, 0.f);
    }

    float mmax = -CUDART_INF_F;
    float lsum = 0.f;

    const int kt_max = (qt * 128 + 127) >> 6;
    for (int kt = 0; kt <= kt_max; kt++) {
        const float4* kbase = (const float4*)(g_k + ((size_t)(b * LL + kt * 64)) * DD + h * DH);
        const float4* vbase = (const float4*)(g_v + ((size_t)(b * LL + kt * 64)) * DD + h * DH);
        __syncthreads();
        #pragma unroll
        for (int i = tid; i < 64 * 16; i += 128) {
            int row = i >> 4, c4 = i & 15;
            Ks[row][c4] = kbase[(size_t)row * (DD / 4) + c4];
            Vs[row][c4] = vbase[(size_t)row * (DD / 4) + c4];
        }
        __syncthreads();

        const int jmax = min(63, r - kt * 64);
        for (int j = 0; j <= jmax; j++) {
            float s = 0.f;
            #pragma unroll
            for (int d = 0; d < 16; d++) {
                float4 kk = Ks[j][d];
                s += q4[d].x * kk.x + q4[d].y * kk.y + q4[d].z * kk.z + q4[d].w * kk.w;
            }

            if (s > mmax) {
                float corr = __expf(mmax - s);
                lsum *= corr;
                #pragma unroll
                for (int d = 0; d < 16; d++) {
                    o4[d].x *= corr; o4[d].y *= corr; o4[d].z *= corr; o4[d].w *= corr;
                }
                mmax = s;
            }
            float p = __expf(s - mmax);
            lsum += p;
            #pragma unroll
            for (int d = 0; d < 16; d++) {
                float4 vv = Vs[j][d];
                o4[d].x += p * vv.x; o4[d].y += p * vv.y;
                o4[d].z += p * vv.z; o4[d].w += p * vv.w;
            }
        }
    }

    const float invl = 1.f / lsum;
    float4* yptr = (float4*)(g_y + ((size_t)(b * LL + r)) * DD + h * DH);
    #pragma unroll
    for (int d = 0; d < 16; d++)
        yptr[d] = make_float4(o4[d].x * invl, o4[d].y * invl, o4[d].z * invl, o4[d].w * invl);
}

// ---------------------------------------------------------------------------
extern "C" void kernel_launch(void* const* d_in, const int* in_sizes, int n_in,
                              void* d_out, int out_size) {
    const float* x  = (const float*)d_in[0];
    const float* Wq = (const float*)d_in[1];
    const float* Wk = (const float*)d_in[2];
    const float* Wv = (const float*)d_in[3];
    const float* Wo = (const float*)d_in[4];
    float* out = (float*)d_out;

    float *q, *k, *v, *y;
    cudaGetSymbolAddress((void**)&q, g_q);
    cudaGetSymbolAddress((void**)&k, g_k);
    cudaGetSymbolAddress((void**)&v, g_v);
    cudaGetSymbolAddress((void**)&y, g_y);

    dim3 ggrid(DD / BN, MM / BM);      // (8, 32)
    const float qscale = 1.0f / 32.0f; // 1/sqrt(1024)

    gemm_mma<<<ggrid, 256>>>(x, Wq, q, qscale);
    gemm_mma<<<ggrid, 256>>>(x, Wk, k, 1.0f);
    gemm_mma<<<ggrid, 256>>>(x, Wv, v, 1.0f);

    int npairs = MM * (DD / 2);
    rope_kernel<<<(npairs + 255) / 256, 256>>>(q, k);

    dim3 agrid(LL / 128, BB * HH);
    flash_attn<<<agrid, 128>>>();

    gemm_mma<<<ggrid, 256>>>(y, Wo, out, 1.0f);
}

// round 6
// speedup vs baseline: 3.6030x; 1.9374x over previous
#include <cuda_runtime.h>
#include <math_constants.h>
#include <cstdint>

// Problem constants (fixed by the dataset)
#define BB 2
#define LL 2048
#define DD 1024
#define HH 16
#define DH 64
#define MM (BB*LL)   // 4096 rows

// GEMM tiling
#define BM 128
#define BN 128
#define BKG 16
#define NIT (DD / BKG)        // 64
#define APAD 4
#define LDA (BM + APAD)       // 132 floats: As[k][m]
#define LDB (BN + APAD)       // 132 floats: Bs[k][n]

// Attention smem strides
#define LDK 68
#define LDV 65

// Scratch (allocation-free rule: __device__ globals)
__device__ float g_q[MM*DD];
__device__ float g_k[MM*DD];
__device__ float g_v[MM*DD];
__device__ float g_y[MM*DD];

// ---------------------------------------------------------------------------
__device__ __forceinline__ float tf32r(float x) {
    uint32_t u;
    asm("cvt.rna.tf32.f32 %0, %1;" : "=r"(u) : "f"(x));
    return __uint_as_float(u);
}

__device__ __forceinline__ void mma_tf32(float* d, const float* a, const float* b) {
    asm volatile(
        "mma.sync.aligned.m16n8k8.row.col.f32.tf32.tf32.f32 "
        "{%0,%1,%2,%3}, {%4,%5,%6,%7}, {%8,%9}, {%0,%1,%2,%3};\n"
        : "+f"(d[0]), "+f"(d[1]), "+f"(d[2]), "+f"(d[3])
        : "r"(__float_as_uint(a[0])), "r"(__float_as_uint(a[1])),
          "r"(__float_as_uint(a[2])), "r"(__float_as_uint(a[3])),
          "r"(__float_as_uint(b[0])), "r"(__float_as_uint(b[1])));
}

// ---------------------------------------------------------------------------
// tf32 mma.sync GEMM: C[M,1024] = scale * A[M,1024] @ W[1024,1024]
// ---------------------------------------------------------------------------
__global__ __launch_bounds__(256) void gemm_mma(const float* __restrict__ A,
                                                const float* __restrict__ W,
                                                float* __restrict__ C,
                                                float scale) {
    __shared__ float As[2][BKG][LDA];   // [k][m], padded
    __shared__ float Bs[2][BKG][LDB];   // [k][n], padded

    const int tid  = threadIdx.x;
    const int wid  = tid >> 5;
    const int lane = tid & 31;
    const int grp  = lane >> 2;
    const int tig  = lane & 3;
    const int m0   = blockIdx.y * BM;
    const int n0   = blockIdx.x * BN;
    const int wm0  = (wid >> 1) * 32;
    const int wn0  = (wid & 1) * 64;

    float acc[2][8][4];
    #pragma unroll
    for (int mt = 0; mt < 2; mt++)
        #pragma unroll
        for (int nt = 0; nt < 8; nt++)
            #pragma unroll
            for (int r = 0; r < 4; r++) acc[mt][nt][r] = 0.f;

    const int am[2] = { tid >> 2, (tid + 256) >> 2 };
    const int akq = tid & 3;
    const int bk[2] = { tid >> 5, (tid + 256) >> 5 };
    const int bnq = tid & 31;

    float4 ra[2], rb[2];

    auto loadT = [&](int it) {
        const int k0 = it * BKG;
        #pragma unroll
        for (int j = 0; j < 2; j++) {
            ra[j] = *(const float4*)(A + (size_t)(m0 + am[j]) * DD + k0 + akq * 4);
            rb[j] = *(const float4*)(W + (size_t)(k0 + bk[j]) * DD + n0 + bnq * 4);
        }
    };
    auto storeT = [&](int buf) {
        #pragma unroll
        for (int j = 0; j < 2; j++) {
            As[buf][akq * 4 + 0][am[j]] = tf32r(ra[j].x);
            As[buf][akq * 4 + 1][am[j]] = tf32r(ra[j].y);
            As[buf][akq * 4 + 2][am[j]] = tf32r(ra[j].z);
            As[buf][akq * 4 + 3][am[j]] = tf32r(ra[j].w);
            float4 t = make_float4(tf32r(rb[j].x), tf32r(rb[j].y),
                                   tf32r(rb[j].z), tf32r(rb[j].w));
            *(float4*)&Bs[buf][bk[j]][bnq * 4] = t;
        }
    };

    loadT(0);
    storeT(0);
    __syncthreads();

    for (int it = 0; it < NIT; it++) {
        const int buf = it & 1;
        if (it + 1 < NIT) loadT(it + 1);

        #pragma unroll
        for (int ks = 0; ks < 2; ks++) {
            const int kb = ks * 8;
            float a[2][4], b[8][2];
            #pragma unroll
            for (int mt = 0; mt < 2; mt++) {
                const int m = wm0 + mt * 16;
                a[mt][0] = As[buf][kb + tig    ][m + grp];
                a[mt][1] = As[buf][kb + tig    ][m + grp + 8];
                a[mt][2] = As[buf][kb + tig + 4][m + grp];
                a[mt][3] = As[buf][kb + tig + 4][m + grp + 8];
            }
            #pragma unroll
            for (int nt = 0; nt < 8; nt++) {
                const int n = wn0 + nt * 8;
                b[nt][0] = Bs[buf][kb + tig    ][n + grp];
                b[nt][1] = Bs[buf][kb + tig + 4][n + grp];
            }
            #pragma unroll
            for (int mt = 0; mt < 2; mt++)
                #pragma unroll
                for (int nt = 0; nt < 8; nt++)
                    mma_tf32(acc[mt][nt], a[mt], b[nt]);
        }

        if (it + 1 < NIT) storeT(buf ^ 1);
        __syncthreads();
    }

    #pragma unroll
    for (int mt = 0; mt < 2; mt++) {
        #pragma unroll
        for (int nt = 0; nt < 8; nt++) {
            const int m = m0 + wm0 + mt * 16 + grp;
            const int n = n0 + wn0 + nt * 8 + 2 * tig;
            float2 lo = make_float2(acc[mt][nt][0] * scale, acc[mt][nt][1] * scale);
            float2 hi = make_float2(acc[mt][nt][2] * scale, acc[mt][nt][3] * scale);
            *(float2*)(C + (size_t)m * DD + n) = lo;
            *(float2*)(C + (size_t)(m + 8) * DD + n) = hi;
        }
    }
}

// ---------------------------------------------------------------------------
// RoPE on q and k (in place).
// ---------------------------------------------------------------------------
__global__ __launch_bounds__(256) void rope_kernel(float* __restrict__ q,
                                                   float* __restrict__ k) {
    int idx = blockIdx.x * blockDim.x + threadIdx.x;
    if (idx >= MM * (DD / 2)) return;
    int row = idx / (DD / 2);
    int pc  = idx % (DD / 2);
    int pos = row & (LL - 1);
    int hc  = pc & (DH / 2 - 1);

    float inv = exp2f(-(float)hc * 0.41524101186092029f);
    float ang = (float)pos * inv;
    float s = sinf(ang), c = cosf(ang);

    float2* qp = (float2*)q;
    float2* kp = (float2*)k;
    float2 vq = qp[idx];
    qp[idx] = make_float2(vq.x * c - vq.y * s, vq.y * c + vq.x * s);
    float2 vk = kp[idx];
    kp[idx] = make_float2(vk.x * c - vk.y * s, vk.y * c + vk.x * s);
}

// ---------------------------------------------------------------------------
// Tensor-core flash attention (tf32 mma.sync).
// Grid: (32 q-tiles reversed, 32 bh). Block 128 = 4 warps x 16 query rows.
// Key tiles of 64; online softmax in mma accumulator layout.
// Static smem only (34 KB): K tile + transposed V tile. Q fragments from gmem.
// ---------------------------------------------------------------------------
__global__ __launch_bounds__(128) void flash_attn_mma() {
    __shared__ float Ks[64][LDK];
    __shared__ float Vt[64][LDV];

    const int qt  = (int)gridDim.x - 1 - blockIdx.x;   // heavy tiles first
    const int bh  = blockIdx.y;
    const int b   = bh >> 4;
    const int h   = bh & 15;
    const int tid = threadIdx.x;
    const int wid = tid >> 5;
    const int lane = tid & 31;
    const int grp = lane >> 2;
    const int tig = lane & 3;
    const int q0  = qt * 64;
    const int row0 = q0 + wid * 16 + grp;   // rows row0 and row0+8

    // Q fragments straight from gmem (read once, L2-resident)
    float qa[8][4];
    {
        const float* qr0 = g_q + ((size_t)(b * LL + row0)) * DD + h * DH;
        const float* qr1 = qr0 + (size_t)8 * DD;
        #pragma unroll
        for (int kt = 0; kt < 8; kt++) {
            qa[kt][0] = tf32r(qr0[kt * 8 + tig]);
            qa[kt][1] = tf32r(qr1[kt * 8 + tig]);
            qa[kt][2] = tf32r(qr0[kt * 8 + tig + 4]);
            qa[kt][3] = tf32r(qr1[kt * 8 + tig + 4]);
        }
    }

    float o[8][4];
    #pragma unroll
    for (int dt = 0; dt < 8; dt++)
        #pragma unroll
        for (int r = 0; r < 4; r++) o[dt][r] = 0.f;
    float m0 = -CUDART_INF_F, m1 = -CUDART_INF_F;
    float l0 = 0.f, l1 = 0.f;

    for (int kt0 = 0; kt0 <= qt; kt0++) {
        const int kb = kt0 * 64;
        __syncthreads();   // previous tile fully consumed
        #pragma unroll
        for (int it = 0; it < 8; it++) {
            int idx = it * 128 + tid;
            int jr = idx >> 4, dq = idx & 15;
            const size_t rowoff = ((size_t)(b * LL + kb + jr)) * DD + h * DH + dq * 4;
            const float4 tk = *(const float4*)(g_k + rowoff);
            *(float4*)&Ks[jr][dq * 4] = make_float4(tf32r(tk.x), tf32r(tk.y), tf32r(tk.z), tf32r(tk.w));
            const float4 tv = *(const float4*)(g_v + rowoff);
            Vt[dq * 4 + 0][jr] = tf32r(tv.x);
            Vt[dq * 4 + 1][jr] = tf32r(tv.y);
            Vt[dq * 4 + 2][jr] = tf32r(tv.z);
            Vt[dq * 4 + 3][jr] = tf32r(tv.w);
        }
        __syncthreads();

        // S = Q K^T for this tile: 8 n-tiles x 8 k-steps
        float s[8][4];
        #pragma unroll
        for (int nt = 0; nt < 8; nt++)
            #pragma unroll
            for (int r = 0; r < 4; r++) s[nt][r] = 0.f;
        #pragma unroll
        for (int kk = 0; kk < 8; kk++) {
            #pragma unroll
            for (int nt = 0; nt < 8; nt++) {
                float bfr[2] = { Ks[nt * 8 + grp][kk * 8 + tig],
                                 Ks[nt * 8 + grp][kk * 8 + tig + 4] };
                mma_tf32(s[nt], qa[kk], bfr);
            }
        }

        // causal mask (diagonal tile only)
        if (kt0 == qt) {
            #pragma unroll
            for (int nt = 0; nt < 8; nt++) {
                const int j = kb + nt * 8 + 2 * tig;
                if (j     > row0)     s[nt][0] = -CUDART_INF_F;
                if (j + 1 > row0)     s[nt][1] = -CUDART_INF_F;
                if (j     > row0 + 8) s[nt][2] = -CUDART_INF_F;
                if (j + 1 > row0 + 8) s[nt][3] = -CUDART_INF_F;
            }
        }

        // online softmax
        float t0 = s[0][0], t1 = s[0][2];
        #pragma unroll
        for (int nt = 0; nt < 8; nt++) {
            t0 = fmaxf(t0, fmaxf(s[nt][0], s[nt][1]));
            t1 = fmaxf(t1, fmaxf(s[nt][2], s[nt][3]));
        }
        t0 = fmaxf(t0, __shfl_xor_sync(0xffffffffu, t0, 1));
        t0 = fmaxf(t0, __shfl_xor_sync(0xffffffffu, t0, 2));
        t1 = fmaxf(t1, __shfl_xor_sync(0xffffffffu, t1, 1));
        t1 = fmaxf(t1, __shfl_xor_sync(0xffffffffu, t1, 2));
        const float mn0 = fmaxf(m0, t0), mn1 = fmaxf(m1, t1);
        const float c0 = __expf(m0 - mn0), c1 = __expf(m1 - mn1);
        m0 = mn0; m1 = mn1;
        l0 *= c0; l1 *= c1;
        #pragma unroll
        for (int dt = 0; dt < 8; dt++) {
            o[dt][0] *= c0; o[dt][1] *= c0;
            o[dt][2] *= c1; o[dt][3] *= c1;
        }
        #pragma unroll
        for (int nt = 0; nt < 8; nt++) {
            s[nt][0] = tf32r(__expf(s[nt][0] - m0));
            s[nt][1] = tf32r(__expf(s[nt][1] - m0));
            s[nt][2] = tf32r(__expf(s[nt][2] - m1));
            s[nt][3] = tf32r(__expf(s[nt][3] - m1));
            l0 += s[nt][0] + s[nt][1];
            l1 += s[nt][2] + s[nt][3];
        }

        // O += P V : remap P from C-layout to A-layout via shuffles
        const int srclo = (grp << 2) + (tig >> 1);
        const bool par = (tig & 1);
        #pragma unroll
        for (int kk = 0; kk < 8; kk++) {
            float w00 = __shfl_sync(0xffffffffu, s[kk][0], srclo);
            float w01 = __shfl_sync(0xffffffffu, s[kk][1], srclo);
            float w10 = __shfl_sync(0xffffffffu, s[kk][2], srclo);
            float w11 = __shfl_sync(0xffffffffu, s[kk][3], srclo);
            float x00 = __shfl_sync(0xffffffffu, s[kk][0], srclo + 2);
            float x01 = __shfl_sync(0xffffffffu, s[kk][1], srclo + 2);
            float x10 = __shfl_sync(0xffffffffu, s[kk][2], srclo + 2);
            float x11 = __shfl_sync(0xffffffffu, s[kk][3], srclo + 2);
            float pa[4];
            pa[0] = par ? w01 : w00;
            pa[1] = par ? w11 : w10;
            pa[2] = par ? x01 : x00;
            pa[3] = par ? x11 : x10;
            #pragma unroll
            for (int dt = 0; dt < 8; dt++) {
                float bfr[2] = { Vt[dt * 8 + grp][kk * 8 + tig],
                                 Vt[dt * 8 + grp][kk * 8 + tig + 4] };
                mma_tf32(o[dt], pa, bfr);
            }
        }
    }

    // final normalize + store
    l0 += __shfl_xor_sync(0xffffffffu, l0, 1);
    l0 += __shfl_xor_sync(0xffffffffu, l0, 2);
    l1 += __shfl_xor_sync(0xffffffffu, l1, 1);
    l1 += __shfl_xor_sync(0xffffffffu, l1, 2);
    const float i0 = 1.f / l0, i1 = 1.f / l1;
    float* y0 = g_y + ((size_t)(b * LL + row0)) * DD + h * DH;
    float* y1 = y0 + (size_t)8 * DD;
    #pragma unroll
    for (int dt = 0; dt < 8; dt++) {
        *(float2*)(y0 + dt * 8 + 2 * tig) = make_float2(o[dt][0] * i0, o[dt][1] * i0);
        *(float2*)(y1 + dt * 8 + 2 * tig) = make_float2(o[dt][2] * i1, o[dt][3] * i1);
    }
}

// ---------------------------------------------------------------------------
extern "C" void kernel_launch(void* const* d_in, const int* in_sizes, int n_in,
                              void* d_out, int out_size) {
    const float* x  = (const float*)d_in[0];
    const float* Wq = (const float*)d_in[1];
    const float* Wk = (const float*)d_in[2];
    const float* Wv = (const float*)d_in[3];
    const float* Wo = (const float*)d_in[4];
    float* out = (float*)d_out;

    float *q, *k, *v, *y;
    cudaGetSymbolAddress((void**)&q, g_q);
    cudaGetSymbolAddress((void**)&k, g_k);
    cudaGetSymbolAddress((void**)&v, g_v);
    cudaGetSymbolAddress((void**)&y, g_y);

    dim3 ggrid(DD / BN, MM / BM);      // (8, 32)
    const float qscale = 1.0f / 32.0f; // 1/sqrt(1024)

    gemm_mma<<<ggrid, 256>>>(x, Wq, q, qscale);
    gemm_mma<<<ggrid, 256>>>(x, Wk, k, 1.0f);
    gemm_mma<<<ggrid, 256>>>(x, Wv, v, 1.0f);

    int npairs = MM * (DD / 2);
    rope_kernel<<<(npairs + 255) / 256, 256>>>(q, k);

    dim3 agrid(32, BB * HH);
    flash_attn_mma<<<agrid, 128>>>();

    gemm_mma<<<ggrid, 256>>>(y, Wo, out, 1.0f);
}

// round 8
// speedup vs baseline: 6.5307x; 1.8126x over previous
#include <cuda_runtime.h>
#include <cuda_fp16.h>
#include <math_constants.h>
#include <cstdint>

// Problem constants (fixed by the dataset)
#define BB 2
#define LL 2048
#define DD 1024
#define HH 16
#define DH 64
#define MM (BB*LL)   // 4096 rows

// GEMM tiling
#define BM 128
#define BN 128
#define BK 32
#define NIT (DD / BK)         // 32
#define LDH 40                // smem row stride in halves (conflict-free: 20 mod 32 = 20)

// Attention smem strides (halves). 72/2=36 ≡ 4 (mod 32) -> conflict-free frag loads
#define LDKh 72
#define LDVh 72

// Scratch (allocation-free rule: __device__ globals), fp16
__device__ __half g_q[MM*DD];
__device__ __half g_k[MM*DD];
__device__ __half g_v[MM*DD];
__device__ __half g_y[MM*DD];
__device__ __half g_wq[DD*DD];   // transposed [n][k]
__device__ __half g_wk[DD*DD];
__device__ __half g_wv[DD*DD];
__device__ __half g_wo[DD*DD];

// ---------------------------------------------------------------------------
__device__ __forceinline__ uint32_t pack2(float lo, float hi) {
    __half2 h = __floats2half2_rn(lo, hi);
    return *reinterpret_cast<uint32_t*>(&h);
}

__device__ __forceinline__ void mma_f16(float* d, const uint32_t* a, const uint32_t* b) {
    asm volatile(
        "mma.sync.aligned.m16n8k16.row.col.f32.f16.f16.f32 "
        "{%0,%1,%2,%3}, {%4,%5,%6,%7}, {%8,%9}, {%0,%1,%2,%3};\n"
        : "+f"(d[0]), "+f"(d[1]), "+f"(d[2]), "+f"(d[3])
        : "r"(a[0]), "r"(a[1]), "r"(a[2]), "r"(a[3]), "r"(b[0]), "r"(b[1]));
}

// ---------------------------------------------------------------------------
// Transpose + fp32->fp16 convert: Wt[n][k] = (half)W[k][n]
// ---------------------------------------------------------------------------
__global__ __launch_bounds__(256) void transpose_h(const float* __restrict__ W,
                                                   __half* __restrict__ Wt) {
    __shared__ float t[32][33];
    int tx = threadIdx.x & 31, ty = threadIdx.x >> 5;   // ty 0..7
    int bx = blockIdx.x * 32, by = blockIdx.y * 32;
    #pragma unroll
    for (int i = 0; i < 4; i++)
        t[ty + i * 8][tx] = W[(size_t)(by + ty + i * 8) * DD + bx + tx];
    __syncthreads();
    #pragma unroll
    for (int i = 0; i < 4; i++)
        Wt[(size_t)(bx + ty + i * 8) * DD + by + tx] = __float2half(t[tx][ty + i * 8]);
}

// ---------------------------------------------------------------------------
// fp16 mma.sync GEMM: C[M,1024] = scale * A[M,1024] @ Bt[1024,1024]^T
// A row-major (f32 or f16), Bt [n][k] f16. Block 128x128, BK=32, 8 warps.
// ---------------------------------------------------------------------------
template<bool AHALF, bool CHALF>
__global__ __launch_bounds__(256) void gemm_f16(const void* __restrict__ Ap,
                                                const __half* __restrict__ Bt,
                                                void* __restrict__ Cp,
                                                float scale) {
    __shared__ __half As[2][BM][LDH];   // [m][k]
    __shared__ __half Bs[2][BN][LDH];   // [n][k]

    const int tid  = threadIdx.x;
    const int wid  = tid >> 5;
    const int lane = tid & 31;
    const int grp  = lane >> 2;
    const int tig  = lane & 3;
    const int m0   = blockIdx.y * BM;
    const int n0   = blockIdx.x * BN;
    const int wm0  = (wid >> 1) * 32;
    const int wn0  = (wid & 1) * 64;

    float acc[2][8][4];
    #pragma unroll
    for (int mt = 0; mt < 2; mt++)
        #pragma unroll
        for (int nt = 0; nt < 8; nt++)
            #pragma unroll
            for (int r = 0; r < 4; r++) acc[mt][nt][r] = 0.f;

    float4 raf[4];
    uint4  ra16[2];
    uint4  rbv[2];

    auto loadT = [&](int it) {
        const int k0 = it * BK;
        if (AHALF) {
            const __half* Ah = (const __half*)Ap;
            #pragma unroll
            for (int j = 0; j < 2; j++) {
                int f = j * 256 + tid; int m = f >> 2; int kq = (f & 3) * 8;
                ra16[j] = *(const uint4*)(Ah + (size_t)(m0 + m) * DD + k0 + kq);
            }
        } else {
            const float* Af = (const float*)Ap;
            #pragma unroll
            for (int j = 0; j < 4; j++) {
                int f = j * 256 + tid; int m = f >> 3; int kq = (f & 7) * 4;
                raf[j] = *(const float4*)(Af + (size_t)(m0 + m) * DD + k0 + kq);
            }
        }
        #pragma unroll
        for (int j = 0; j < 2; j++) {
            int f = j * 256 + tid; int n = f >> 2; int kq = (f & 3) * 8;
            rbv[j] = *(const uint4*)(Bt + (size_t)(n0 + n) * DD + k0 + kq);
        }
    };
    auto storeT = [&](int buf) {
        if (AHALF) {
            #pragma unroll
            for (int j = 0; j < 2; j++) {
                int f = j * 256 + tid; int m = f >> 2; int kq = (f & 3) * 8;
                *(uint4*)&As[buf][m][kq] = ra16[j];
            }
        } else {
            #pragma unroll
            for (int j = 0; j < 4; j++) {
                int f = j * 256 + tid; int m = f >> 3; int kq = (f & 7) * 4;
                *(uint32_t*)&As[buf][m][kq]     = pack2(raf[j].x, raf[j].y);
                *(uint32_t*)&As[buf][m][kq + 2] = pack2(raf[j].z, raf[j].w);
            }
        }
        #pragma unroll
        for (int j = 0; j < 2; j++) {
            int f = j * 256 + tid; int n = f >> 2; int kq = (f & 3) * 8;
            *(uint4*)&Bs[buf][n][kq] = rbv[j];
        }
    };

    loadT(0);
    storeT(0);
    __syncthreads();

    for (int it = 0; it < NIT; it++) {
        const int buf = it & 1;
        if (it + 1 < NIT) loadT(it + 1);

        #pragma unroll
        for (int kd = 0; kd < 2; kd++) {
            const int kb = kd * 16;
            uint32_t a[2][4], b[8][2];
            #pragma unroll
            for (int mt = 0; mt < 2; mt++) {
                const int m = wm0 + mt * 16;
                a[mt][0] = *(const uint32_t*)&As[buf][m + grp    ][kb + 2 * tig];
                a[mt][1] = *(const uint32_t*)&As[buf][m + grp + 8][kb + 2 * tig];
                a[mt][2] = *(const uint32_t*)&As[buf][m + grp    ][kb + 2 * tig + 8];
                a[mt][3] = *(const uint32_t*)&As[buf][m + grp + 8][kb + 2 * tig + 8];
            }
            #pragma unroll
            for (int nt = 0; nt < 8; nt++) {
                const int n = wn0 + nt * 8;
                b[nt][0] = *(const uint32_t*)&Bs[buf][n + grp][kb + 2 * tig];
                b[nt][1] = *(const uint32_t*)&Bs[buf][n + grp][kb + 2 * tig + 8];
            }
            #pragma unroll
            for (int mt = 0; mt < 2; mt++)
                #pragma unroll
                for (int nt = 0; nt < 8; nt++)
                    mma_f16(acc[mt][nt], a[mt], b[nt]);
        }

        if (it + 1 < NIT) storeT(buf ^ 1);
        __syncthreads();
    }

    #pragma unroll
    for (int mt = 0; mt < 2; mt++) {
        #pragma unroll
        for (int nt = 0; nt < 8; nt++) {
            const int m = m0 + wm0 + mt * 16 + grp;
            const int n = n0 + wn0 + nt * 8 + 2 * tig;
            if (CHALF) {
                __half* C = (__half*)Cp;
                *(uint32_t*)(C + (size_t)m * DD + n)       = pack2(acc[mt][nt][0] * scale, acc[mt][nt][1] * scale);
                *(uint32_t*)(C + (size_t)(m + 8) * DD + n) = pack2(acc[mt][nt][2] * scale, acc[mt][nt][3] * scale);
            } else {
                float* C = (float*)Cp;
                *(float2*)(C + (size_t)m * DD + n) =
                    make_float2(acc[mt][nt][0] * scale, acc[mt][nt][1] * scale);
                *(float2*)(C + (size_t)(m + 8) * DD + n) =
                    make_float2(acc[mt][nt][2] * scale, acc[mt][nt][3] * scale);
            }
        }
    }
}

// ---------------------------------------------------------------------------
// RoPE on fp16 q and k (in place). One thread per (row, pair).
// ---------------------------------------------------------------------------
__global__ __launch_bounds__(256) void rope_kernel() {
    int idx = blockIdx.x * blockDim.x + threadIdx.x;
    if (idx >= MM * (DD / 2)) return;
    int row = idx / (DD / 2);
    int pc  = idx % (DD / 2);
    int pos = row & (LL - 1);
    int hc  = pc & (DH / 2 - 1);

    float inv = exp2f(-(float)hc * 0.41524101186092029f);  // 10000^(-2hc/64)
    float ang = (float)pos * inv;
    float s = sinf(ang), c = cosf(ang);

    __half2* qp = (__half2*)g_q;
    __half2* kp = (__half2*)g_k;
    float2 vq = __half22float2(qp[idx]);
    qp[idx] = __floats2half2_rn(vq.x * c - vq.y * s, vq.y * c + vq.x * s);
    float2 vk = __half22float2(kp[idx]);
    kp[idx] = __floats2half2_rn(vk.x * c - vk.y * s, vk.y * c + vk.x * s);
}

// ---------------------------------------------------------------------------
// fp16 tensor-core flash attention.
// Grid: (32 q-tiles reversed, 32 bh). Block 128 = 4 warps x 16 query rows.
// Key tiles of 64; online softmax; P remap is thread-local for m16n8k16.
// ---------------------------------------------------------------------------
__global__ __launch_bounds__(128) void flash_attn_f16() {
    __shared__ __half Ks[64][LDKh];   // [key j][d]
    __shared__ __half Vt[64][LDVh];   // [d][key j]

    const int qt  = (int)gridDim.x - 1 - blockIdx.x;   // heavy tiles first
    const int bh  = blockIdx.y;
    const int b   = bh >> 4;
    const int h   = bh & 15;
    const int tid = threadIdx.x;
    const int wid = tid >> 5;
    const int lane = tid & 31;
    const int grp = lane >> 2;
    const int tig = lane & 3;
    const int q0  = qt * 64;
    const int row0 = q0 + wid * 16 + grp;   // rows row0 and row0+8

    // Q fragments straight from gmem (fp16 pairs)
    uint32_t qa[4][4];
    {
        const __half* qr0 = g_q + ((size_t)(b * LL + row0)) * DD + h * DH;
        const __half* qr1 = qr0 + (size_t)8 * DD;
        #pragma unroll
        for (int kd = 0; kd < 4; kd++) {
            qa[kd][0] = *(const uint32_t*)(qr0 + kd * 16 + 2 * tig);
            qa[kd][1] = *(const uint32_t*)(qr1 + kd * 16 + 2 * tig);
            qa[kd][2] = *(const uint32_t*)(qr0 + kd * 16 + 2 * tig + 8);
            qa[kd][3] = *(const uint32_t*)(qr1 + kd * 16 + 2 * tig + 8);
        }
    }

    float o[8][4];
    #pragma unroll
    for (int dt = 0; dt < 8; dt++)
        #pragma unroll
        for (int r = 0; r < 4; r++) o[dt][r] = 0.f;
    float m0 = -CUDART_INF_F, m1 = -CUDART_INF_F;
    float l0 = 0.f, l1 = 0.f;

    for (int kt0 = 0; kt0 <= qt; kt0++) {
        const int kb = kt0 * 64;
        __syncthreads();   // previous tile fully consumed
        #pragma unroll
        for (int it = 0; it < 4; it++) {
            int idx = it * 128 + tid;
            int jr = idx & 63, dq = idx >> 6;   // dq 0..7 -> d = dq*8
            const size_t rowoff = ((size_t)(b * LL + kb + jr)) * DD + h * DH + dq * 8;
            uint4 tk = *(const uint4*)(g_k + rowoff);
            *(uint4*)&Ks[jr][dq * 8] = tk;
            uint4 tv = *(const uint4*)(g_v + rowoff);
            const __half* vh = (const __half*)&tv;
            #pragma unroll
            for (int i = 0; i < 8; i++) Vt[dq * 8 + i][jr] = vh[i];
        }
        __syncthreads();

        // S = Q K^T : 4 k16-steps x 8 n-tiles
        float s[8][4];
        #pragma unroll
        for (int nt = 0; nt < 8; nt++)
            #pragma unroll
            for (int r = 0; r < 4; r++) s[nt][r] = 0.f;
        #pragma unroll
        for (int kd = 0; kd < 4; kd++) {
            #pragma unroll
            for (int nt = 0; nt < 8; nt++) {
                uint32_t bfr[2] = {
                    *(const uint32_t*)&Ks[nt * 8 + grp][kd * 16 + 2 * tig],
                    *(const uint32_t*)&Ks[nt * 8 + grp][kd * 16 + 2 * tig + 8] };
                mma_f16(s[nt], qa[kd], bfr);
            }
        }

        // causal mask (diagonal tile only)
        if (kt0 == qt) {
            #pragma unroll
            for (int nt = 0; nt < 8; nt++) {
                const int j = kb + nt * 8 + 2 * tig;
                if (j     > row0)     s[nt][0] = -CUDART_INF_F;
                if (j + 1 > row0)     s[nt][1] = -CUDART_INF_F;
                if (j     > row0 + 8) s[nt][2] = -CUDART_INF_F;
                if (j + 1 > row0 + 8) s[nt][3] = -CUDART_INF_F;
            }
        }

        // online softmax
        float t0 = s[0][0], t1 = s[0][2];
        #pragma unroll
        for (int nt = 0; nt < 8; nt++) {
            t0 = fmaxf(t0, fmaxf(s[nt][0], s[nt][1]));
            t1 = fmaxf(t1, fmaxf(s[nt][2], s[nt][3]));
        }
        t0 = fmaxf(t0, __shfl_xor_sync(0xffffffffu, t0, 1));
        t0 = fmaxf(t0, __shfl_xor_sync(0xffffffffu, t0, 2));
        t1 = fmaxf(t1, __shfl_xor_sync(0xffffffffu, t1, 1));
        t1 = fmaxf(t1, __shfl_xor_sync(0xffffffffu, t1, 2));
        const float mn0 = fmaxf(m0, t0), mn1 = fmaxf(m1, t1);
        const float c0 = __expf(m0 - mn0), c1 = __expf(m1 - mn1);
        m0 = mn0; m1 = mn1;
        l0 *= c0; l1 *= c1;
        #pragma unroll
        for (int dt = 0; dt < 8; dt++) {
            o[dt][0] *= c0; o[dt][1] *= c0;
            o[dt][2] *= c1; o[dt][3] *= c1;
        }
        #pragma unroll
        for (int nt = 0; nt < 8; nt++) {
            s[nt][0] = __expf(s[nt][0] - m0);
            s[nt][1] = __expf(s[nt][1] - m0);
            s[nt][2] = __expf(s[nt][2] - m1);
            s[nt][3] = __expf(s[nt][3] - m1);
            l0 += s[nt][0] + s[nt][1];
            l1 += s[nt][2] + s[nt][3];
        }

        // O += P V : P A-fragments are thread-local for k16 (no shuffles)
        #pragma unroll
        for (int kk2 = 0; kk2 < 4; kk2++) {
            uint32_t pa[4] = {
                pack2(s[2 * kk2][0],     s[2 * kk2][1]),
                pack2(s[2 * kk2][2],     s[2 * kk2][3]),
                pack2(s[2 * kk2 + 1][0], s[2 * kk2 + 1][1]),
                pack2(s[2 * kk2 + 1][2], s[2 * kk2 + 1][3]) };
            #pragma unroll
            for (int dt = 0; dt < 8; dt++) {
                uint32_t bfr[2] = {
                    *(const uint32_t*)&Vt[dt * 8 + grp][kk2 * 16 + 2 * tig],
                    *(const uint32_t*)&Vt[dt * 8 + grp][kk2 * 16 + 2 * tig + 8] };
                mma_f16(o[dt], pa, bfr);
            }
        }
    }

    // final normalize + store (fp16)
    l0 += __shfl_xor_sync(0xffffffffu, l0, 1);
    l0 += __shfl_xor_sync(0xffffffffu, l0, 2);
    l1 += __shfl_xor_sync(0xffffffffu, l1, 1);
    l1 += __shfl_xor_sync(0xffffffffu, l1, 2);
    const float i0 = 1.f / l0, i1 = 1.f / l1;
    __half* y0 = g_y + ((size_t)(b * LL + row0)) * DD + h * DH;
    __half* y1 = y0 + (size_t)8 * DD;
    #pragma unroll
    for (int dt = 0; dt < 8; dt++) {
        *(uint32_t*)(y0 + dt * 8 + 2 * tig) = pack2(o[dt][0] * i0, o[dt][1] * i0);
        *(uint32_t*)(y1 + dt * 8 + 2 * tig) = pack2(o[dt][2] * i1, o[dt][3] * i1);
    }
}

// ---------------------------------------------------------------------------
extern "C" void kernel_launch(void* const* d_in, const int* in_sizes, int n_in,
                              void* d_out, int out_size) {
    const float* x  = (const float*)d_in[0];
    const float* Wq = (const float*)d_in[1];
    const float* Wk = (const float*)d_in[2];
    const float* Wv = (const float*)d_in[3];
    const float* Wo = (const float*)d_in[4];
    float* out = (float*)d_out;

    __half *q, *k, *v, *y, *wq, *wk, *wv, *wo;
    cudaGetSymbolAddress((void**)&q, g_q);
    cudaGetSymbolAddress((void**)&k, g_k);
    cudaGetSymbolAddress((void**)&v, g_v);
    cudaGetSymbolAddress((void**)&y, g_y);
    cudaGetSymbolAddress((void**)&wq, g_wq);
    cudaGetSymbolAddress((void**)&wk, g_wk);
    cudaGetSymbolAddress((void**)&wv, g_wv);
    cudaGetSymbolAddress((void**)&wo, g_wo);

    dim3 tgrid(DD / 32, DD / 32);
    transpose_h<<<tgrid, 256>>>(Wq, wq);
    transpose_h<<<tgrid, 256>>>(Wk, wk);
    transpose_h<<<tgrid, 256>>>(Wv, wv);
    transpose_h<<<tgrid, 256>>>(Wo, wo);

    dim3 ggrid(DD / BN, MM / BM);      // (8, 32)
    const float qscale = 1.0f / 32.0f; // 1/sqrt(1024)

    gemm_f16<false, true><<<ggrid, 256>>>(x, wq, q, qscale);
    gemm_f16<false, true><<<ggrid, 256>>>(x, wk, k, 1.0f);
    gemm_f16<false, true><<<ggrid, 256>>>(x, wv, v, 1.0f);

    int npairs = MM * (DD / 2);
    rope_kernel<<<(npairs + 255) / 256, 256>>>();

    dim3 agrid(32, BB * HH);
    flash_attn_f16<<<agrid, 128>>>();

    gemm_f16<true, false><<<ggrid, 256>>>(y, wo, out, 1.0f);
}

// round 9
// speedup vs baseline: 10.0316x; 1.5361x over previous
#include <cuda_runtime.h>
#include <cuda_fp16.h>
#include <math_constants.h>
#include <cstdint>

// Problem constants (fixed by the dataset)
#define BB 2
#define LL 2048
#define DD 1024
#define HH 16
#define DH 64
#define MM (BB*LL)   // 4096 rows

// GEMM tiling
#define BM 128
#define BN 128
#define BK 32
#define NIT (DD / BK)         // 32
#define LDH 40                // As row stride (halves): 80B rows, ldmatrix conflict-free
#define LDBH 136              // Bs row stride (halves): 272B rows, conflict-free

// Attention smem stride (halves): 144B rows, conflict-free
#define LDKh 72

// Scratch (allocation-free rule: __device__ globals), fp16
__device__ __half g_x16[MM*DD];
__device__ __half g_q[MM*DD];
__device__ __half g_k[MM*DD];
__device__ __half g_v[MM*DD];
__device__ __half g_y[MM*DD];
__device__ __half g_wq[DD*DD];   // [k][n] halves (no transpose)
__device__ __half g_wk[DD*DD];
__device__ __half g_wv[DD*DD];
__device__ __half g_wo[DD*DD];

// ---------------------------------------------------------------------------
__device__ __forceinline__ uint32_t pack2(float lo, float hi) {
    __half2 h = __floats2half2_rn(lo, hi);
    return *reinterpret_cast<uint32_t*>(&h);
}
__device__ __forceinline__ uint32_t smaddr(const void* p) {
    return (uint32_t)__cvta_generic_to_shared(p);
}

__device__ __forceinline__ void mma_f16(float* d, const uint32_t* a, const uint32_t* b) {
    asm volatile(
        "mma.sync.aligned.m16n8k16.row.col.f32.f16.f16.f32 "
        "{%0,%1,%2,%3}, {%4,%5,%6,%7}, {%8,%9}, {%0,%1,%2,%3};\n"
        : "+f"(d[0]), "+f"(d[1]), "+f"(d[2]), "+f"(d[3])
        : "r"(a[0]), "r"(a[1]), "r"(a[2]), "r"(a[3]), "r"(b[0]), "r"(b[1]));
}
__device__ __forceinline__ void ldsm_x4(uint32_t* r, uint32_t addr) {
    asm volatile("ldmatrix.sync.aligned.m8n8.x4.shared.b16 {%0,%1,%2,%3}, [%4];"
        : "=r"(r[0]), "=r"(r[1]), "=r"(r[2]), "=r"(r[3]) : "r"(addr));
}
__device__ __forceinline__ void ldsm_x4_t(uint32_t* r, uint32_t addr) {
    asm volatile("ldmatrix.sync.aligned.m8n8.x4.trans.shared.b16 {%0,%1,%2,%3}, [%4];"
        : "=r"(r[0]), "=r"(r[1]), "=r"(r[2]), "=r"(r[3]) : "r"(addr));
}

#define CP16(dst_u32, src_ptr) \
    asm volatile("cp.async.cg.shared.global [%0], [%1], 16;" :: "r"(dst_u32), "l"(src_ptr))
#define CPC()  asm volatile("cp.async.commit_group;" ::: "memory")
#define CPW0() asm volatile("cp.async.wait_group 0;" ::: "memory")

// ---------------------------------------------------------------------------
// f32 -> f16 convert (streaming)
// ---------------------------------------------------------------------------
__global__ __launch_bounds__(256) void cvt_h(const float* __restrict__ src,
                                             __half* __restrict__ dst, int n4) {
    int i = blockIdx.x * blockDim.x + threadIdx.x;
    if (i >= n4) return;
    float4 v = ((const float4*)src)[i];
    ((uint2*)dst)[i] = make_uint2(pack2(v.x, v.y), pack2(v.z, v.w));
}

// ---------------------------------------------------------------------------
// fp16 mma.sync GEMM: C[M,1024] = scale * A[M,1024] @ Bk[1024,1024]
// A [m][k] f16, Bk [k][n] f16 (natural layout; B-frags via ldmatrix.trans).
// Block 128x128, BK=32, 8 warps (4m x 2n), cp.async 2-stage pipeline.
// ---------------------------------------------------------------------------
template<bool CHALF>
__global__ __launch_bounds__(256) void gemm_f16(const __half* __restrict__ A,
                                                const __half* __restrict__ Bk,
                                                void* __restrict__ Cp,
                                                float scale) {
    __shared__ __half As[2][BM][LDH];    // [m][k]
    __shared__ __half Bs[2][BK][LDBH];   // [k][n]

    const int tid  = threadIdx.x;
    const int wid  = tid >> 5;
    const int lane = tid & 31;
    const int grp  = lane >> 2;
    const int tig  = lane & 3;
    const int tile = lane >> 3;      // ldmatrix tile id
    const int tr   = lane & 7;       // ldmatrix row-in-tile
    const int m0   = blockIdx.y * BM;
    const int n0   = blockIdx.x * BN;
    const int wm0  = (wid >> 1) * 32;
    const int wn0  = (wid & 1) * 64;

    float acc[2][8][4];
    #pragma unroll
    for (int mt = 0; mt < 2; mt++)
        #pragma unroll
        for (int nt = 0; nt < 8; nt++)
            #pragma unroll
            for (int r = 0; r < 4; r++) acc[mt][nt][r] = 0.f;

    auto load = [&](int it, int buf) {
        const int k0 = it * BK;
        #pragma unroll
        for (int j = 0; j < 2; j++) {            // A: 512 x 16B chunks
            int c = tid + j * 256;
            int row = c >> 2, q = c & 3;
            CP16(smaddr(&As[buf][row][q * 8]), A + (size_t)(m0 + row) * DD + k0 + q * 8);
        }
        #pragma unroll
        for (int j = 0; j < 2; j++) {            // B: 512 x 16B chunks
            int c = tid + j * 256;
            int row = c >> 4, q = c & 15;
            CP16(smaddr(&Bs[buf][row][q * 8]), Bk + (size_t)(k0 + row) * DD + n0 + q * 8);
        }
    };

    load(0, 0); CPC();

    for (int it = 0; it < NIT; it++) {
        const int buf = it & 1;
        CPW0();
        __syncthreads();
        if (it + 1 < NIT) { load(it + 1, buf ^ 1); CPC(); }

        #pragma unroll
        for (int kd = 0; kd < 2; kd++) {
            const int kb = kd * 16;
            uint32_t a[2][4], bfr[4][4];
            #pragma unroll
            for (int mt = 0; mt < 2; mt++) {
                int mrow = wm0 + mt * 16 + tr + ((tile & 1) ? 8 : 0);
                int kcol = kb + ((tile >= 2) ? 8 : 0);
                ldsm_x4(a[mt], smaddr(&As[buf][mrow][kcol]));
            }
            #pragma unroll
            for (int p = 0; p < 4; p++) {        // n-pairs: nt = 2p, 2p+1
                int krow = kb + tr + ((tile & 1) ? 8 : 0);
                int ncol = wn0 + 16 * p + ((tile >= 2) ? 8 : 0);
                ldsm_x4_t(bfr[p], smaddr(&Bs[buf][krow][ncol]));
            }
            #pragma unroll
            for (int mt = 0; mt < 2; mt++)
                #pragma unroll
                for (int p = 0; p < 4; p++) {
                    mma_f16(acc[mt][2 * p],     a[mt], &bfr[p][0]);
                    mma_f16(acc[mt][2 * p + 1], a[mt], &bfr[p][2]);
                }
        }
    }

    #pragma unroll
    for (int mt = 0; mt < 2; mt++) {
        #pragma unroll
        for (int nt = 0; nt < 8; nt++) {
            const int m = m0 + wm0 + mt * 16 + grp;
            const int n = n0 + wn0 + nt * 8 + 2 * tig;
            if (CHALF) {
                __half* C = (__half*)Cp;
                *(uint32_t*)(C + (size_t)m * DD + n)       = pack2(acc[mt][nt][0] * scale, acc[mt][nt][1] * scale);
                *(uint32_t*)(C + (size_t)(m + 8) * DD + n) = pack2(acc[mt][nt][2] * scale, acc[mt][nt][3] * scale);
            } else {
                float* C = (float*)Cp;
                *(float2*)(C + (size_t)m * DD + n) =
                    make_float2(acc[mt][nt][0] * scale, acc[mt][nt][1] * scale);
                *(float2*)(C + (size_t)(m + 8) * DD + n) =
                    make_float2(acc[mt][nt][2] * scale, acc[mt][nt][3] * scale);
            }
        }
    }
}

// ---------------------------------------------------------------------------
// RoPE on fp16 q and k (in place). One thread per (row, pair).
// ---------------------------------------------------------------------------
__global__ __launch_bounds__(256) void rope_kernel() {
    int idx = blockIdx.x * blockDim.x + threadIdx.x;
    if (idx >= MM * (DD / 2)) return;
    int row = idx / (DD / 2);
    int pc  = idx % (DD / 2);
    int pos = row & (LL - 1);
    int hc  = pc & (DH / 2 - 1);

    float inv = exp2f(-(float)hc * 0.41524101186092029f);  // 10000^(-2hc/64)
    float ang = (float)pos * inv;
    float s = sinf(ang), c = cosf(ang);

    __half2* qp = (__half2*)g_q;
    __half2* kp = (__half2*)g_k;
    float2 vq = __half22float2(qp[idx]);
    qp[idx] = __floats2half2_rn(vq.x * c - vq.y * s, vq.y * c + vq.x * s);
    float2 vk = __half22float2(kp[idx]);
    kp[idx] = __floats2half2_rn(vk.x * c - vk.y * s, vk.y * c + vk.x * s);
}

// ---------------------------------------------------------------------------
// fp16 tensor-core flash attention with ldmatrix + cp.async K/V pipeline.
// Grid: (32 q-tiles reversed, 32 bh). Block 128 = 4 warps x 16 query rows.
// K and V both stored row-major [j][d]; V fragments via ldmatrix.trans.
// ---------------------------------------------------------------------------
__global__ __launch_bounds__(128) void flash_attn_f16() {
    __shared__ __half Ks[2][64][LDKh];   // [key j][d]
    __shared__ __half Vs[2][64][LDKh];   // [key j][d]

    const int qt  = (int)gridDim.x - 1 - blockIdx.x;   // heavy tiles first
    const int bh  = blockIdx.y;
    const int b   = bh >> 4;
    const int h   = bh & 15;
    const int tid = threadIdx.x;
    const int wid = tid >> 5;
    const int lane = tid & 31;
    const int grp = lane >> 2;
    const int tig = lane & 3;
    const int tile = lane >> 3;
    const int tr   = lane & 7;
    const int q0  = qt * 64;
    const int row0 = q0 + wid * 16 + grp;   // rows row0 and row0+8

    auto loadKV = [&](int kt, int buf) {
        const int kb = kt * 64;
        #pragma unroll
        for (int j = 0; j < 4; j++) {     // 512 chunks K + 512 chunks V
            int c = tid + j * 128;
            int row = c >> 3, q = c & 7;
            size_t off = (size_t)(b * LL + kb + row) * DD + h * DH + q * 8;
            CP16(smaddr(&Ks[buf][row][q * 8]), g_k + off);
            CP16(smaddr(&Vs[buf][row][q * 8]), g_v + off);
        }
    };

    // Q fragments straight from gmem (fp16 pairs)
    uint32_t qa[4][4];
    {
        const __half* qr0 = g_q + ((size_t)(b * LL + row0)) * DD + h * DH;
        const __half* qr1 = qr0 + (size_t)8 * DD;
        #pragma unroll
        for (int kd = 0; kd < 4; kd++) {
            qa[kd][0] = *(const uint32_t*)(qr0 + kd * 16 + 2 * tig);
            qa[kd][1] = *(const uint32_t*)(qr1 + kd * 16 + 2 * tig);
            qa[kd][2] = *(const uint32_t*)(qr0 + kd * 16 + 2 * tig + 8);
            qa[kd][3] = *(const uint32_t*)(qr1 + kd * 16 + 2 * tig + 8);
        }
    }

    float o[8][4];
    #pragma unroll
    for (int dt = 0; dt < 8; dt++)
        #pragma unroll
        for (int r = 0; r < 4; r++) o[dt][r] = 0.f;
    float m0 = -CUDART_INF_F, m1 = -CUDART_INF_F;
    float l0 = 0.f, l1 = 0.f;

    loadKV(0, 0); CPC();

    for (int kt0 = 0; kt0 <= qt; kt0++) {
        const int kb = kt0 * 64;
        const int buf = kt0 & 1;
        CPW0();
        __syncthreads();
        if (kt0 < qt) { loadKV(kt0 + 1, buf ^ 1); CPC(); }

        // S = Q K^T : 4 k16-steps, B-frags via ldmatrix (non-trans, [j][d]=[n][k])
        float s[8][4];
        #pragma unroll
        for (int nt = 0; nt < 8; nt++)
            #pragma unroll
            for (int r = 0; r < 4; r++) s[nt][r] = 0.f;
        #pragma unroll
        for (int kd = 0; kd < 4; kd++) {
            uint32_t bfr[4][4];
            #pragma unroll
            for (int p = 0; p < 4; p++) {    // key-pairs: nt = 2p, 2p+1
                int nrow = 16 * p + tr + ((tile >= 2) ? 8 : 0);
                int kcol = kd * 16 + ((tile & 1) ? 8 : 0);
                ldsm_x4(bfr[p], smaddr(&Ks[buf][nrow][kcol]));
            }
            #pragma unroll
            for (int p = 0; p < 4; p++) {
                mma_f16(s[2 * p],     qa[kd], &bfr[p][0]);
                mma_f16(s[2 * p + 1], qa[kd], &bfr[p][2]);
            }
        }

        // causal mask (diagonal tile only)
        if (kt0 == qt) {
            #pragma unroll
            for (int nt = 0; nt < 8; nt++) {
                const int j = kb + nt * 8 + 2 * tig;
                if (j     > row0)     s[nt][0] = -CUDART_INF_F;
                if (j + 1 > row0)     s[nt][1] = -CUDART_INF_F;
                if (j     > row0 + 8) s[nt][2] = -CUDART_INF_F;
                if (j + 1 > row0 + 8) s[nt][3] = -CUDART_INF_F;
            }
        }

        // online softmax
        float t0 = s[0][0], t1 = s[0][2];
        #pragma unroll
        for (int nt = 0; nt < 8; nt++) {
            t0 = fmaxf(t0, fmaxf(s[nt][0], s[nt][1]));
            t1 = fmaxf(t1, fmaxf(s[nt][2], s[nt][3]));
        }
        t0 = fmaxf(t0, __shfl_xor_sync(0xffffffffu, t0, 1));
        t0 = fmaxf(t0, __shfl_xor_sync(0xffffffffu, t0, 2));
        t1 = fmaxf(t1, __shfl_xor_sync(0xffffffffu, t1, 1));
        t1 = fmaxf(t1, __shfl_xor_sync(0xffffffffu, t1, 2));
        const float mn0 = fmaxf(m0, t0), mn1 = fmaxf(m1, t1);
        const float c0 = __expf(m0 - mn0), c1 = __expf(m1 - mn1);
        m0 = mn0; m1 = mn1;
        l0 *= c0; l1 *= c1;
        #pragma unroll
        for (int dt = 0; dt < 8; dt++) {
            o[dt][0] *= c0; o[dt][1] *= c0;
            o[dt][2] *= c1; o[dt][3] *= c1;
        }
        #pragma unroll
        for (int nt = 0; nt < 8; nt++) {
            s[nt][0] = __expf(s[nt][0] - m0);
            s[nt][1] = __expf(s[nt][1] - m0);
            s[nt][2] = __expf(s[nt][2] - m1);
            s[nt][3] = __expf(s[nt][3] - m1);
            l0 += s[nt][0] + s[nt][1];
            l1 += s[nt][2] + s[nt][3];
        }

        // O += P V : P thread-local; V frags via ldmatrix.trans from [j][d]
        #pragma unroll
        for (int kk2 = 0; kk2 < 4; kk2++) {
            uint32_t pa[4] = {
                pack2(s[2 * kk2][0],     s[2 * kk2][1]),
                pack2(s[2 * kk2][2],     s[2 * kk2][3]),
                pack2(s[2 * kk2 + 1][0], s[2 * kk2 + 1][1]),
                pack2(s[2 * kk2 + 1][2], s[2 * kk2 + 1][3]) };
            uint32_t bfr[4][4];
            #pragma unroll
            for (int p = 0; p < 4; p++) {    // d-pairs: dt = 2p, 2p+1
                int jrow = kk2 * 16 + tr + ((tile & 1) ? 8 : 0);
                int dcol = 16 * p + ((tile >= 2) ? 8 : 0);
                ldsm_x4_t(bfr[p], smaddr(&Vs[buf][jrow][dcol]));
            }
            #pragma unroll
            for (int p = 0; p < 4; p++) {
                mma_f16(o[2 * p],     pa, &bfr[p][0]);
                mma_f16(o[2 * p + 1], pa, &bfr[p][2]);
            }
        }
    }

    // final normalize + store (fp16)
    l0 += __shfl_xor_sync(0xffffffffu, l0, 1);
    l0 += __shfl_xor_sync(0xffffffffu, l0, 2);
    l1 += __shfl_xor_sync(0xffffffffu, l1, 1);
    l1 += __shfl_xor_sync(0xffffffffu, l1, 2);
    const float i0 = 1.f / l0, i1 = 1.f / l1;
    __half* y0 = g_y + ((size_t)(b * LL + row0)) * DD + h * DH;
    __half* y1 = y0 + (size_t)8 * DD;
    #pragma unroll
    for (int dt = 0; dt < 8; dt++) {
        *(uint32_t*)(y0 + dt * 8 + 2 * tig) = pack2(o[dt][0] * i0, o[dt][1] * i0);
        *(uint32_t*)(y1 + dt * 8 + 2 * tig) = pack2(o[dt][2] * i1, o[dt][3] * i1);
    }
}

// ---------------------------------------------------------------------------
extern "C" void kernel_launch(void* const* d_in, const int* in_sizes, int n_in,
                              void* d_out, int out_size) {
    const float* x  = (const float*)d_in[0];
    const float* Wq = (const float*)d_in[1];
    const float* Wk = (const float*)d_in[2];
    const float* Wv = (const float*)d_in[3];
    const float* Wo = (const float*)d_in[4];
    float* out = (float*)d_out;

    __half *x16, *q, *k, *v, *y, *wq, *wk, *wv, *wo;
    cudaGetSymbolAddress((void**)&x16, g_x16);
    cudaGetSymbolAddress((void**)&q, g_q);
    cudaGetSymbolAddress((void**)&k, g_k);
    cudaGetSymbolAddress((void**)&v, g_v);
    cudaGetSymbolAddress((void**)&y, g_y);
    cudaGetSymbolAddress((void**)&wq, g_wq);
    cudaGetSymbolAddress((void**)&wk, g_wk);
    cudaGetSymbolAddress((void**)&wv, g_wv);
    cudaGetSymbolAddress((void**)&wo, g_wo);

    const int nx4 = MM * DD / 4, nw4 = DD * DD / 4;
    cvt_h<<<(nx4 + 255) / 256, 256>>>(x, x16, nx4);
    cvt_h<<<(nw4 + 255) / 256, 256>>>(Wq, wq, nw4);
    cvt_h<<<(nw4 + 255) / 256, 256>>>(Wk, wk, nw4);
    cvt_h<<<(nw4 + 255) / 256, 256>>>(Wv, wv, nw4);
    cvt_h<<<(nw4 + 255) / 256, 256>>>(Wo, wo, nw4);

    dim3 ggrid(DD / BN, MM / BM);      // (8, 32)
    const float qscale = 1.0f / 32.0f; // 1/sqrt(1024)

    gemm_f16<true><<<ggrid, 256>>>(x16, wq, q, qscale);
    gemm_f16<true><<<ggrid, 256>>>(x16, wk, k, 1.0f);
    gemm_f16<true><<<ggrid, 256>>>(x16, wv, v, 1.0f);

    int npairs = MM * (DD / 2);
    rope_kernel<<<(npairs + 255) / 256, 256>>>();

    dim3 agrid(32, BB * HH);
    flash_attn_f16<<<agrid, 128>>>();

    gemm_f16<false><<<ggrid, 256>>>(y, wo, out, 1.0f);
}

// round 10
// speedup vs baseline: 10.2797x; 1.0247x over previous
#include <cuda_runtime.h>
#include <cuda_fp16.h>
#include <math_constants.h>
#include <cstdint>

// Problem constants (fixed by the dataset)
#define BB 2
#define LL 2048
#define DD 1024
#define HH 16
#define DH 64
#define MM (BB*LL)   // 4096 rows

// GEMM tiling
#define BM 128
#define BN 128
#define BK 32
#define NIT (DD / BK)         // 32
#define LDH 40                // As row stride (halves)
#define LDBH 136              // Bs row stride (halves)

// Attention smem stride (halves)
#define LDKh 72

// Scratch (allocation-free rule: __device__ globals), fp16
__device__ __half g_x16[MM*DD];
__device__ __half g_q[MM*DD];
__device__ __half g_k[MM*DD];
__device__ __half g_v[MM*DD];
__device__ __half g_y[MM*DD];
__device__ __half g_wq[DD*DD];   // [k][n] halves
__device__ __half g_wk[DD*DD];
__device__ __half g_wv[DD*DD];
__device__ __half g_wo[DD*DD];

// ---------------------------------------------------------------------------
__device__ __forceinline__ uint32_t pack2(float lo, float hi) {
    __half2 h = __floats2half2_rn(lo, hi);
    return *reinterpret_cast<uint32_t*>(&h);
}
__device__ __forceinline__ uint32_t smaddr(const void* p) {
    return (uint32_t)__cvta_generic_to_shared(p);
}

__device__ __forceinline__ void mma_f16(float* d, const uint32_t* a, const uint32_t* b) {
    asm volatile(
        "mma.sync.aligned.m16n8k16.row.col.f32.f16.f16.f32 "
        "{%0,%1,%2,%3}, {%4,%5,%6,%7}, {%8,%9}, {%0,%1,%2,%3};\n"
        : "+f"(d[0]), "+f"(d[1]), "+f"(d[2]), "+f"(d[3])
        : "r"(a[0]), "r"(a[1]), "r"(a[2]), "r"(a[3]), "r"(b[0]), "r"(b[1]));
}
__device__ __forceinline__ void ldsm_x4(uint32_t* r, uint32_t addr) {
    asm volatile("ldmatrix.sync.aligned.m8n8.x4.shared.b16 {%0,%1,%2,%3}, [%4];"
        : "=r"(r[0]), "=r"(r[1]), "=r"(r[2]), "=r"(r[3]) : "r"(addr));
}
__device__ __forceinline__ void ldsm_x4_t(uint32_t* r, uint32_t addr) {
    asm volatile("ldmatrix.sync.aligned.m8n8.x4.trans.shared.b16 {%0,%1,%2,%3}, [%4];"
        : "=r"(r[0]), "=r"(r[1]), "=r"(r[2]), "=r"(r[3]) : "r"(addr));
}

#define CP16(dst_u32, src_ptr) \
    asm volatile("cp.async.cg.shared.global [%0], [%1], 16;" :: "r"(dst_u32), "l"(src_ptr))
#define CPC()  asm volatile("cp.async.commit_group;" ::: "memory")
#define CPW0() asm volatile("cp.async.wait_group 0;" ::: "memory")

// ---------------------------------------------------------------------------
// Fused f32 -> f16 convert of x + 4 weight matrices (one launch).
// ---------------------------------------------------------------------------
#define NX4 (MM * DD / 4)
#define NW4 (DD * DD / 4)
__global__ __launch_bounds__(256) void cvt_all(const float* __restrict__ x,
                                               const float* __restrict__ Wq,
                                               const float* __restrict__ Wk,
                                               const float* __restrict__ Wv,
                                               const float* __restrict__ Wo) {
    int i = blockIdx.x * blockDim.x + threadIdx.x;   // over NX4 + 4*NW4
    const float* src;
    __half* dst;
    int off;
    if (i < NX4)                { src = x;  dst = g_x16; off = i; }
    else if (i < NX4 + NW4)     { src = Wq; dst = g_wq;  off = i - NX4; }
    else if (i < NX4 + 2*NW4)   { src = Wk; dst = g_wk;  off = i - NX4 - NW4; }
    else if (i < NX4 + 3*NW4)   { src = Wv; dst = g_wv;  off = i - NX4 - 2*NW4; }
    else                        { src = Wo; dst = g_wo;  off = i - NX4 - 3*NW4; }
    float4 v = ((const float4*)src)[off];
    ((uint2*)dst)[off] = make_uint2(pack2(v.x, v.y), pack2(v.z, v.w));
}

// ---------------------------------------------------------------------------
// fp16 mma.sync GEMM: C = scale * A @ Bk, A [m][k], Bk [k][n].
// Fused-QKV variant: blockIdx.z in {0,1,2} selects (Wq->q), (Wk->k), (Wv->v).
// ---------------------------------------------------------------------------
__device__ __forceinline__ void gemm_body(const __half* __restrict__ A,
                                          const __half* __restrict__ Bk,
                                          void* __restrict__ Cp,
                                          float scale, bool chalf,
                                          int m0, int n0) {
    __shared__ __half As[2][BM][LDH];    // [m][k]
    __shared__ __half Bs[2][BK][LDBH];   // [k][n]

    const int tid  = threadIdx.x;
    const int wid  = tid >> 5;
    const int lane = tid & 31;
    const int grp  = lane >> 2;
    const int tig  = lane & 3;
    const int tile = lane >> 3;
    const int tr   = lane & 7;
    const int wm0  = (wid >> 1) * 32;
    const int wn0  = (wid & 1) * 64;

    float acc[2][8][4];
    #pragma unroll
    for (int mt = 0; mt < 2; mt++)
        #pragma unroll
        for (int nt = 0; nt < 8; nt++)
            #pragma unroll
            for (int r = 0; r < 4; r++) acc[mt][nt][r] = 0.f;

    auto load = [&](int it, int buf) {
        const int k0 = it * BK;
        #pragma unroll
        for (int j = 0; j < 2; j++) {
            int c = tid + j * 256;
            int row = c >> 2, q = c & 3;
            CP16(smaddr(&As[buf][row][q * 8]), A + (size_t)(m0 + row) * DD + k0 + q * 8);
        }
        #pragma unroll
        for (int j = 0; j < 2; j++) {
            int c = tid + j * 256;
            int row = c >> 4, q = c & 15;
            CP16(smaddr(&Bs[buf][row][q * 8]), Bk + (size_t)(k0 + row) * DD + n0 + q * 8);
        }
    };

    load(0, 0); CPC();

    for (int it = 0; it < NIT; it++) {
        const int buf = it & 1;
        CPW0();
        __syncthreads();
        if (it + 1 < NIT) { load(it + 1, buf ^ 1); CPC(); }

        #pragma unroll
        for (int kd = 0; kd < 2; kd++) {
            const int kb = kd * 16;
            uint32_t a[2][4], bfr[4][4];
            #pragma unroll
            for (int mt = 0; mt < 2; mt++) {
                int mrow = wm0 + mt * 16 + tr + ((tile & 1) ? 8 : 0);
                int kcol = kb + ((tile >= 2) ? 8 : 0);
                ldsm_x4(a[mt], smaddr(&As[buf][mrow][kcol]));
            }
            #pragma unroll
            for (int p = 0; p < 4; p++) {
                int krow = kb + tr + ((tile & 1) ? 8 : 0);
                int ncol = wn0 + 16 * p + ((tile >= 2) ? 8 : 0);
                ldsm_x4_t(bfr[p], smaddr(&Bs[buf][krow][ncol]));
            }
            #pragma unroll
            for (int mt = 0; mt < 2; mt++)
                #pragma unroll
                for (int p = 0; p < 4; p++) {
                    mma_f16(acc[mt][2 * p],     a[mt], &bfr[p][0]);
                    mma_f16(acc[mt][2 * p + 1], a[mt], &bfr[p][2]);
                }
        }
    }

    #pragma unroll
    for (int mt = 0; mt < 2; mt++) {
        #pragma unroll
        for (int nt = 0; nt < 8; nt++) {
            const int m = m0 + wm0 + mt * 16 + grp;
            const int n = n0 + wn0 + nt * 8 + 2 * tig;
            if (chalf) {
                __half* C = (__half*)Cp;
                *(uint32_t*)(C + (size_t)m * DD + n)       = pack2(acc[mt][nt][0] * scale, acc[mt][nt][1] * scale);
                *(uint32_t*)(C + (size_t)(m + 8) * DD + n) = pack2(acc[mt][nt][2] * scale, acc[mt][nt][3] * scale);
            } else {
                float* C = (float*)Cp;
                *(float2*)(C + (size_t)m * DD + n) =
                    make_float2(acc[mt][nt][0] * scale, acc[mt][nt][1] * scale);
                *(float2*)(C + (size_t)(m + 8) * DD + n) =
                    make_float2(acc[mt][nt][2] * scale, acc[mt][nt][3] * scale);
            }
        }
    }
}

__global__ __launch_bounds__(256) void gemm_qkv() {
    const __half* W = (blockIdx.z == 0) ? g_wq : (blockIdx.z == 1) ? g_wk : g_wv;
    __half* C       = (blockIdx.z == 0) ? g_q  : (blockIdx.z == 1) ? g_k  : g_v;
    float scale     = (blockIdx.z == 0) ? (1.0f / 32.0f) : 1.0f;
    gemm_body(g_x16, W, C, scale, true, blockIdx.y * BM, blockIdx.x * BN);
}

__global__ __launch_bounds__(256) void gemm_out(float* __restrict__ out) {
    gemm_body(g_y, g_wo, out, 1.0f, false, blockIdx.y * BM, blockIdx.x * BN);
}

// ---------------------------------------------------------------------------
// RoPE on fp16 q and k (in place).
// ---------------------------------------------------------------------------
__global__ __launch_bounds__(256) void rope_kernel() {
    int idx = blockIdx.x * blockDim.x + threadIdx.x;
    if (idx >= MM * (DD / 2)) return;
    int row = idx / (DD / 2);
    int pc  = idx % (DD / 2);
    int pos = row & (LL - 1);
    int hc  = pc & (DH / 2 - 1);

    float inv = exp2f(-(float)hc * 0.41524101186092029f);  // 10000^(-2hc/64)
    float ang = (float)pos * inv;
    float s = sinf(ang), c = cosf(ang);

    __half2* qp = (__half2*)g_q;
    __half2* kp = (__half2*)g_k;
    float2 vq = __half22float2(qp[idx]);
    qp[idx] = __floats2half2_rn(vq.x * c - vq.y * s, vq.y * c + vq.x * s);
    float2 vk = __half22float2(kp[idx]);
    kp[idx] = __floats2half2_rn(vk.x * c - vk.y * s, vk.y * c + vk.x * s);
}

// ---------------------------------------------------------------------------
// fp16 tensor-core flash attention, 128-query CTAs (8 warps x 16 rows).
// Key tiles of 64; per-warp uniform skip of fully-masked tiles.
// ---------------------------------------------------------------------------
__global__ __launch_bounds__(256) void flash_attn_f16() {
    __shared__ __half Ks[2][64][LDKh];   // [key j][d]
    __shared__ __half Vs[2][64][LDKh];   // [key j][d]

    const int qt  = (int)gridDim.x - 1 - blockIdx.x;   // heavy tiles first
    const int bh  = blockIdx.y;
    const int b   = bh >> 4;
    const int h   = bh & 15;
    const int tid = threadIdx.x;
    const int wid = tid >> 5;
    const int lane = tid & 31;
    const int grp = lane >> 2;
    const int tig = lane & 3;
    const int tile = lane >> 3;
    const int tr   = lane & 7;
    const int q0  = qt * 128;
    const int wrow = q0 + wid * 16;          // warp's first row
    const int row0 = wrow + grp;             // rows row0 and row0+8
    const int kt_max = (q0 + 127) >> 6;      // inclusive: 2*qt+1

    auto loadKV = [&](int kt, int buf) {
        const int kb = kt * 64;
        #pragma unroll
        for (int j = 0; j < 2; j++) {     // 512 chunks K + 512 chunks V
            int c = tid + j * 256;
            int row = c >> 3, q = c & 7;
            size_t off = (size_t)(b * LL + kb + row) * DD + h * DH + q * 8;
            CP16(smaddr(&Ks[buf][row][q * 8]), g_k + off);
            CP16(smaddr(&Vs[buf][row][q * 8]), g_v + off);
        }
    };

    // Q fragments straight from gmem (fp16 pairs)
    uint32_t qa[4][4];
    {
        const __half* qr0 = g_q + ((size_t)(b * LL + row0)) * DD + h * DH;
        const __half* qr1 = qr0 + (size_t)8 * DD;
        #pragma unroll
        for (int kd = 0; kd < 4; kd++) {
            qa[kd][0] = *(const uint32_t*)(qr0 + kd * 16 + 2 * tig);
            qa[kd][1] = *(const uint32_t*)(qr1 + kd * 16 + 2 * tig);
            qa[kd][2] = *(const uint32_t*)(qr0 + kd * 16 + 2 * tig + 8);
            qa[kd][3] = *(const uint32_t*)(qr1 + kd * 16 + 2 * tig + 8);
        }
    }

    float o[8][4];
    #pragma unroll
    for (int dt = 0; dt < 8; dt++)
        #pragma unroll
        for (int r = 0; r < 4; r++) o[dt][r] = 0.f;
    float m0 = -CUDART_INF_F, m1 = -CUDART_INF_F;
    float l0 = 0.f, l1 = 0.f;

    loadKV(0, 0); CPC();

    for (int kt0 = 0; kt0 <= kt_max; kt0++) {
        const int kb = kt0 * 64;
        const int buf = kt0 & 1;
        CPW0();
        __syncthreads();
        if (kt0 < kt_max) { loadKV(kt0 + 1, buf ^ 1); CPC(); }

        // per-warp uniform skip: tile fully masked for this warp's rows
        if (kb <= wrow + 15) {
            // S = Q K^T
            float s[8][4];
            #pragma unroll
            for (int nt = 0; nt < 8; nt++)
                #pragma unroll
                for (int r = 0; r < 4; r++) s[nt][r] = 0.f;
            #pragma unroll
            for (int kd = 0; kd < 4; kd++) {
                uint32_t bfr[4][4];
                #pragma unroll
                for (int p = 0; p < 4; p++) {
                    int nrow = 16 * p + tr + ((tile >= 2) ? 8 : 0);
                    int kcol = kd * 16 + ((tile & 1) ? 8 : 0);
                    ldsm_x4(bfr[p], smaddr(&Ks[buf][nrow][kcol]));
                }
                #pragma unroll
                for (int p = 0; p < 4; p++) {
                    mma_f16(s[2 * p],     qa[kd], &bfr[p][0]);
                    mma_f16(s[2 * p + 1], qa[kd], &bfr[p][2]);
                }
            }

            // causal mask (tiles overlapping this warp's diagonal)
            if (kb + 63 > wrow) {
                #pragma unroll
                for (int nt = 0; nt < 8; nt++) {
                    const int j = kb + nt * 8 + 2 * tig;
                    if (j     > row0)     s[nt][0] = -CUDART_INF_F;
                    if (j + 1 > row0)     s[nt][1] = -CUDART_INF_F;
                    if (j     > row0 + 8) s[nt][2] = -CUDART_INF_F;
                    if (j + 1 > row0 + 8) s[nt][3] = -CUDART_INF_F;
                }
            }

            // online softmax
            float t0 = s[0][0], t1 = s[0][2];
            #pragma unroll
            for (int nt = 0; nt < 8; nt++) {
                t0 = fmaxf(t0, fmaxf(s[nt][0], s[nt][1]));
                t1 = fmaxf(t1, fmaxf(s[nt][2], s[nt][3]));
            }
            t0 = fmaxf(t0, __shfl_xor_sync(0xffffffffu, t0, 1));
            t0 = fmaxf(t0, __shfl_xor_sync(0xffffffffu, t0, 2));
            t1 = fmaxf(t1, __shfl_xor_sync(0xffffffffu, t1, 1));
            t1 = fmaxf(t1, __shfl_xor_sync(0xffffffffu, t1, 2));
            const float mn0 = fmaxf(m0, t0), mn1 = fmaxf(m1, t1);
            const float c0 = __expf(m0 - mn0), c1 = __expf(m1 - mn1);
            m0 = mn0; m1 = mn1;
            l0 *= c0; l1 *= c1;
            #pragma unroll
            for (int dt = 0; dt < 8; dt++) {
                o[dt][0] *= c0; o[dt][1] *= c0;
                o[dt][2] *= c1; o[dt][3] *= c1;
            }
            #pragma unroll
            for (int nt = 0; nt < 8; nt++) {
                s[nt][0] = __expf(s[nt][0] - m0);
                s[nt][1] = __expf(s[nt][1] - m0);
                s[nt][2] = __expf(s[nt][2] - m1);
                s[nt][3] = __expf(s[nt][3] - m1);
                l0 += s[nt][0] + s[nt][1];
                l1 += s[nt][2] + s[nt][3];
            }

            // O += P V
            #pragma unroll
            for (int kk2 = 0; kk2 < 4; kk2++) {
                uint32_t pa[4] = {
                    pack2(s[2 * kk2][0],     s[2 * kk2][1]),
                    pack2(s[2 * kk2][2],     s[2 * kk2][3]),
                    pack2(s[2 * kk2 + 1][0], s[2 * kk2 + 1][1]),
                    pack2(s[2 * kk2 + 1][2], s[2 * kk2 + 1][3]) };
                uint32_t bfr[4][4];
                #pragma unroll
                for (int p = 0; p < 4; p++) {
                    int jrow = kk2 * 16 + tr + ((tile & 1) ? 8 : 0);
                    int dcol = 16 * p + ((tile >= 2) ? 8 : 0);
                    ldsm_x4_t(bfr[p], smaddr(&Vs[buf][jrow][dcol]));
                }
                #pragma unroll
                for (int p = 0; p < 4; p++) {
                    mma_f16(o[2 * p],     pa, &bfr[p][0]);
                    mma_f16(o[2 * p + 1], pa, &bfr[p][2]);
                }
            }
        }
    }

    // final normalize + store (fp16)
    l0 += __shfl_xor_sync(0xffffffffu, l0, 1);
    l0 += __shfl_xor_sync(0xffffffffu, l0, 2);
    l1 += __shfl_xor_sync(0xffffffffu, l1, 1);
    l1 += __shfl_xor_sync(0xffffffffu, l1, 2);
    const float i0 = 1.f / l0, i1 = 1.f / l1;
    __half* y0 = g_y + ((size_t)(b * LL + row0)) * DD + h * DH;
    __half* y1 = y0 + (size_t)8 * DD;
    #pragma unroll
    for (int dt = 0; dt < 8; dt++) {
        *(uint32_t*)(y0 + dt * 8 + 2 * tig) = pack2(o[dt][0] * i0, o[dt][1] * i0);
        *(uint32_t*)(y1 + dt * 8 + 2 * tig) = pack2(o[dt][2] * i1, o[dt][3] * i1);
    }
}

// ---------------------------------------------------------------------------
extern "C" void kernel_launch(void* const* d_in, const int* in_sizes, int n_in,
                              void* d_out, int out_size) {
    const float* x  = (const float*)d_in[0];
    const float* Wq = (const float*)d_in[1];
    const float* Wk = (const float*)d_in[2];
    const float* Wv = (const float*)d_in[3];
    const float* Wo = (const float*)d_in[4];
    float* out = (float*)d_out;

    const int ntot = NX4 + 4 * NW4;
    cvt_all<<<(ntot + 255) / 256, 256>>>(x, Wq, Wk, Wv, Wo);

    dim3 qkvgrid(DD / BN, MM / BM, 3);   // (8, 32, 3)
    gemm_qkv<<<qkvgrid, 256>>>();

    int npairs = MM * (DD / 2);
    rope_kernel<<<(npairs + 255) / 256, 256>>>();

    dim3 agrid(16, BB * HH);
    flash_attn_f16<<<agrid, 256>>>();

    dim3 ggrid(DD / BN, MM / BM);        // (8, 32)
    gemm_out<<<ggrid, 256>>>(out);
}

// round 12
// speedup vs baseline: 10.5223x; 1.0236x over previous
#include <cuda_runtime.h>
#include <cuda_fp16.h>
#include <math_constants.h>
#include <cstdint>

// Problem constants (fixed by the dataset)
#define BB 2
#define LL 2048
#define DD 1024
#define HH 16
#define DH 64
#define MM (BB*LL)   // 4096 rows

// GEMM tiling
#define BM 128
#define BN 128
#define BK 32
#define NIT (DD / BK)         // 32
#define LDH 40                // As row stride (halves)
#define LDBH 136              // Bs row stride (halves)

// Attention smem stride (halves)
#define LDKh 72

// Scratch (allocation-free rule: __device__ globals), fp16
__device__ __half g_x16[MM*DD];
__device__ __half g_q[MM*DD];
__device__ __half g_k[MM*DD];
__device__ __half g_v[MM*DD];
__device__ __half g_y[MM*DD];
__device__ __half g_wq[DD*DD];   // [k][n] halves
__device__ __half g_wk[DD*DD];
__device__ __half g_wv[DD*DD];
__device__ __half g_wo[DD*DD];

// ---------------------------------------------------------------------------
__device__ __forceinline__ uint32_t pack2(float lo, float hi) {
    __half2 h = __floats2half2_rn(lo, hi);
    return *reinterpret_cast<uint32_t*>(&h);
}
__device__ __forceinline__ uint32_t smaddr(const void* p) {
    return (uint32_t)__cvta_generic_to_shared(p);
}
__device__ __forceinline__ float exp2a(float x) {
    float r;
    asm("ex2.approx.f32 %0, %1;" : "=f"(r) : "f"(x));
    return r;
}

__device__ __forceinline__ void mma_f16(float* d, const uint32_t* a, const uint32_t* b) {
    asm volatile(
        "mma.sync.aligned.m16n8k16.row.col.f32.f16.f16.f32 "
        "{%0,%1,%2,%3}, {%4,%5,%6,%7}, {%8,%9}, {%0,%1,%2,%3};\n"
        : "+f"(d[0]), "+f"(d[1]), "+f"(d[2]), "+f"(d[3])
        : "r"(a[0]), "r"(a[1]), "r"(a[2]), "r"(a[3]), "r"(b[0]), "r"(b[1]));
}
__device__ __forceinline__ void ldsm_x4(uint32_t* r, uint32_t addr) {
    asm volatile("ldmatrix.sync.aligned.m8n8.x4.shared.b16 {%0,%1,%2,%3}, [%4];"
        : "=r"(r[0]), "=r"(r[1]), "=r"(r[2]), "=r"(r[3]) : "r"(addr));
}
__device__ __forceinline__ void ldsm_x4_t(uint32_t* r, uint32_t addr) {
    asm volatile("ldmatrix.sync.aligned.m8n8.x4.trans.shared.b16 {%0,%1,%2,%3}, [%4];"
        : "=r"(r[0]), "=r"(r[1]), "=r"(r[2]), "=r"(r[3]) : "r"(addr));
}

#define CP16(dst_u32, src_ptr) \
    asm volatile("cp.async.cg.shared.global [%0], [%1], 16;" :: "r"(dst_u32), "l"(src_ptr))
#define CPC()  asm volatile("cp.async.commit_group;" ::: "memory")
#define CPW0() asm volatile("cp.async.wait_group 0;" ::: "memory")

// ---------------------------------------------------------------------------
// Fused f32 -> f16 convert of x + 4 weight matrices (one launch).
// ---------------------------------------------------------------------------
#define NX4 (MM * DD / 4)
#define NW4 (DD * DD / 4)
__global__ __launch_bounds__(256) void cvt_all(const float* __restrict__ x,
                                               const float* __restrict__ Wq,
                                               const float* __restrict__ Wk,
                                               const float* __restrict__ Wv,
                                               const float* __restrict__ Wo) {
    int i = blockIdx.x * blockDim.x + threadIdx.x;   // over NX4 + 4*NW4
    const float* src;
    __half* dst;
    int off;
    if (i < NX4)                { src = x;  dst = g_x16; off = i; }
    else if (i < NX4 + NW4)     { src = Wq; dst = g_wq;  off = i - NX4; }
    else if (i < NX4 + 2*NW4)   { src = Wk; dst = g_wk;  off = i - NX4 - NW4; }
    else if (i < NX4 + 3*NW4)   { src = Wv; dst = g_wv;  off = i - NX4 - 2*NW4; }
    else                        { src = Wo; dst = g_wo;  off = i - NX4 - 3*NW4; }
    float4 v = ((const float4*)src)[off];
    ((uint2*)dst)[off] = make_uint2(pack2(v.x, v.y), pack2(v.z, v.w));
}

// ---------------------------------------------------------------------------
// fp16 mma.sync GEMM: C = scale * A @ Bk, A [m][k], Bk [k][n].
// ---------------------------------------------------------------------------
__device__ __forceinline__ void gemm_body(const __half* __restrict__ A,
                                          const __half* __restrict__ Bk,
                                          void* __restrict__ Cp,
                                          float scale, bool chalf,
                                          int m0, int n0) {
    __shared__ __half As[2][BM][LDH];    // [m][k]
    __shared__ __half Bs[2][BK][LDBH];   // [k][n]

    const int tid  = threadIdx.x;
    const int wid  = tid >> 5;
    const int lane = tid & 31;
    const int grp  = lane >> 2;
    const int tig  = lane & 3;
    const int tile = lane >> 3;
    const int tr   = lane & 7;
    const int wm0  = (wid >> 1) * 32;
    const int wn0  = (wid & 1) * 64;

    float acc[2][8][4];
    #pragma unroll
    for (int mt = 0; mt < 2; mt++)
        #pragma unroll
        for (int nt = 0; nt < 8; nt++)
            #pragma unroll
            for (int r = 0; r < 4; r++) acc[mt][nt][r] = 0.f;

    auto load = [&](int it, int buf) {
        const int k0 = it * BK;
        #pragma unroll
        for (int j = 0; j < 2; j++) {
            int c = tid + j * 256;
            int row = c >> 2, q = c & 3;
            CP16(smaddr(&As[buf][row][q * 8]), A + (size_t)(m0 + row) * DD + k0 + q * 8);
        }
        #pragma unroll
        for (int j = 0; j < 2; j++) {
            int c = tid + j * 256;
            int row = c >> 4, q = c & 15;
            CP16(smaddr(&Bs[buf][row][q * 8]), Bk + (size_t)(k0 + row) * DD + n0 + q * 8);
        }
    };

    load(0, 0); CPC();

    for (int it = 0; it < NIT; it++) {
        const int buf = it & 1;
        CPW0();
        __syncthreads();
        if (it + 1 < NIT) { load(it + 1, buf ^ 1); CPC(); }

        #pragma unroll
        for (int kd = 0; kd < 2; kd++) {
            const int kb = kd * 16;
            uint32_t a[2][4], bfr[4][4];
            #pragma unroll
            for (int mt = 0; mt < 2; mt++) {
                int mrow = wm0 + mt * 16 + tr + ((tile & 1) ? 8 : 0);
                int kcol = kb + ((tile >= 2) ? 8 : 0);
                ldsm_x4(a[mt], smaddr(&As[buf][mrow][kcol]));
            }
            #pragma unroll
            for (int p = 0; p < 4; p++) {
                int krow = kb + tr + ((tile & 1) ? 8 : 0);
                int ncol = wn0 + 16 * p + ((tile >= 2) ? 8 : 0);
                ldsm_x4_t(bfr[p], smaddr(&Bs[buf][krow][ncol]));
            }
            #pragma unroll
            for (int mt = 0; mt < 2; mt++)
                #pragma unroll
                for (int p = 0; p < 4; p++) {
                    mma_f16(acc[mt][2 * p],     a[mt], &bfr[p][0]);
                    mma_f16(acc[mt][2 * p + 1], a[mt], &bfr[p][2]);
                }
        }
    }

    #pragma unroll
    for (int mt = 0; mt < 2; mt++) {
        #pragma unroll
        for (int nt = 0; nt < 8; nt++) {
            const int m = m0 + wm0 + mt * 16 + grp;
            const int n = n0 + wn0 + nt * 8 + 2 * tig;
            if (chalf) {
                __half* C = (__half*)Cp;
                *(uint32_t*)(C + (size_t)m * DD + n)       = pack2(acc[mt][nt][0] * scale, acc[mt][nt][1] * scale);
                *(uint32_t*)(C + (size_t)(m + 8) * DD + n) = pack2(acc[mt][nt][2] * scale, acc[mt][nt][3] * scale);
            } else {
                float* C = (float*)Cp;
                *(float2*)(C + (size_t)m * DD + n) =
                    make_float2(acc[mt][nt][0] * scale, acc[mt][nt][1] * scale);
                *(float2*)(C + (size_t)(m + 8) * DD + n) =
                    make_float2(acc[mt][nt][2] * scale, acc[mt][nt][3] * scale);
            }
        }
    }
}

// q absorbs 1/sqrt(d) AND log2(e) so softmax runs in exp2 domain (rope is linear).
#define QSCALE 0.04508422002778011f   // log2(e) / 32

__global__ __launch_bounds__(256) void gemm_qkv() {
    const __half* W = (blockIdx.z == 0) ? g_wq : (blockIdx.z == 1) ? g_wk : g_wv;
    __half* C       = (blockIdx.z == 0) ? g_q  : (blockIdx.z == 1) ? g_k  : g_v;
    float scale     = (blockIdx.z == 0) ? QSCALE : 1.0f;
    gemm_body(g_x16, W, C, scale, true, blockIdx.y * BM, blockIdx.x * BN);
}

__global__ __launch_bounds__(256) void gemm_out(float* __restrict__ out) {
    gemm_body(g_y, g_wo, out, 1.0f, false, blockIdx.y * BM, blockIdx.x * BN);
}

// ---------------------------------------------------------------------------
// RoPE on fp16 q and k (in place).
// ---------------------------------------------------------------------------
__global__ __launch_bounds__(256) void rope_kernel() {
    int idx = blockIdx.x * blockDim.x + threadIdx.x;
    if (idx >= MM * (DD / 2)) return;
    int row = idx / (DD / 2);
    int pc  = idx % (DD / 2);
    int pos = row & (LL - 1);
    int hc  = pc & (DH / 2 - 1);

    float inv = exp2f(-(float)hc * 0.41524101186092029f);  // 10000^(-2hc/64)
    float ang = (float)pos * inv;
    float s = sinf(ang), c = cosf(ang);

    __half2* qp = (__half2*)g_q;
    __half2* kp = (__half2*)g_k;
    float2 fq = __half22float2(qp[idx]);
    qp[idx] = __floats2half2_rn(fq.x * c - fq.y * s, fq.y * c + fq.x * s);
    float2 fk = __half22float2(kp[idx]);
    kp[idx] = __floats2half2_rn(fk.x * c - fk.y * s, fk.y * c + fk.x * s);
}

// ---------------------------------------------------------------------------
// fp16 tensor-core flash attention, 128-query CTAs (8 warps x 16 rows).
// exp2-domain softmax; row-sums l accumulated by ones-MMA on the tensor pipe.
// ---------------------------------------------------------------------------
#define ONES2 0x3C003C00u   // half2(1.0, 1.0)

__global__ __launch_bounds__(256, 2) void flash_attn_f16() {
    __shared__ __half Ks[2][64][LDKh];   // [key j][d]
    __shared__ __half Vs[2][64][LDKh];   // [key j][d]

    const int qt  = (int)gridDim.x - 1 - blockIdx.x;   // heavy tiles first
    const int bh  = blockIdx.y;
    const int b   = bh >> 4;
    const int h   = bh & 15;
    const int tid = threadIdx.x;
    const int wid = tid >> 5;
    const int lane = tid & 31;
    const int grp = lane >> 2;
    const int tig = lane & 3;
    const int tile = lane >> 3;
    const int tr   = lane & 7;
    const int q0  = qt * 128;
    const int wrow = q0 + wid * 16;          // warp's first row
    const int row0 = wrow + grp;             // rows row0 and row0+8
    const int kt_max = (q0 + 127) >> 6;      // inclusive

    auto loadKV = [&](int kt, int buf) {
        const int kb = kt * 64;
        #pragma unroll
        for (int j = 0; j < 2; j++) {
            int c = tid + j * 256;
            int row = c >> 3, q = c & 7;
            size_t off = (size_t)(b * LL + kb + row) * DD + h * DH + q * 8;
            CP16(smaddr(&Ks[buf][row][q * 8]), g_k + off);
            CP16(smaddr(&Vs[buf][row][q * 8]), g_v + off);
        }
    };

    // Q fragments straight from gmem (fp16 pairs)
    uint32_t qa[4][4];
    {
        const __half* qr0 = g_q + ((size_t)(b * LL + row0)) * DD + h * DH;
        const __half* qr1 = qr0 + (size_t)8 * DD;
        #pragma unroll
        for (int kd = 0; kd < 4; kd++) {
            qa[kd][0] = *(const uint32_t*)(qr0 + kd * 16 + 2 * tig);
            qa[kd][1] = *(const uint32_t*)(qr1 + kd * 16 + 2 * tig);
            qa[kd][2] = *(const uint32_t*)(qr0 + kd * 16 + 2 * tig + 8);
            qa[kd][3] = *(const uint32_t*)(qr1 + kd * 16 + 2 * tig + 8);
        }
    }

    float o[8][4];
    #pragma unroll
    for (int dt = 0; dt < 8; dt++)
        #pragma unroll
        for (int r = 0; r < 4; r++) o[dt][r] = 0.f;
    float lacc[4] = {0.f, 0.f, 0.f, 0.f};    // row sums via ones-MMA ([0],[2] used)
    float m0 = -CUDART_INF_F, m1 = -CUDART_INF_F;

    loadKV(0, 0); CPC();

    for (int kt0 = 0; kt0 <= kt_max; kt0++) {
        const int kb = kt0 * 64;
        const int buf = kt0 & 1;
        CPW0();
        __syncthreads();
        if (kt0 < kt_max) { loadKV(kt0 + 1, buf ^ 1); CPC(); }

        if (kb <= wrow + 15) {
            // S = Q K^T  (logits already in log2 domain via QSCALE)
            float s[8][4];
            #pragma unroll
            for (int nt = 0; nt < 8; nt++)
                #pragma unroll
                for (int r = 0; r < 4; r++) s[nt][r] = 0.f;
            #pragma unroll
            for (int kd = 0; kd < 4; kd++) {
                uint32_t bfr[4][4];
                #pragma unroll
                for (int p = 0; p < 4; p++) {
                    int nrow = 16 * p + tr + ((tile >= 2) ? 8 : 0);
                    int kcol = kd * 16 + ((tile & 1) ? 8 : 0);
                    ldsm_x4(bfr[p], smaddr(&Ks[buf][nrow][kcol]));
                }
                #pragma unroll
                for (int p = 0; p < 4; p++) {
                    mma_f16(s[2 * p],     qa[kd], &bfr[p][0]);
                    mma_f16(s[2 * p + 1], qa[kd], &bfr[p][2]);
                }
            }

            // causal mask (tiles overlapping this warp's diagonal)
            if (kb + 63 > wrow) {
                #pragma unroll
                for (int nt = 0; nt < 8; nt++) {
                    const int j = kb + nt * 8 + 2 * tig;
                    if (j     > row0)     s[nt][0] = -CUDART_INF_F;
                    if (j + 1 > row0)     s[nt][1] = -CUDART_INF_F;
                    if (j     > row0 + 8) s[nt][2] = -CUDART_INF_F;
                    if (j + 1 > row0 + 8) s[nt][3] = -CUDART_INF_F;
                }
            }

            // online softmax (exp2 domain)
            float t0 = s[0][0], t1 = s[0][2];
            #pragma unroll
            for (int nt = 0; nt < 8; nt++) {
                t0 = fmaxf(t0, fmaxf(s[nt][0], s[nt][1]));
                t1 = fmaxf(t1, fmaxf(s[nt][2], s[nt][3]));
            }
            t0 = fmaxf(t0, __shfl_xor_sync(0xffffffffu, t0, 1));
            t0 = fmaxf(t0, __shfl_xor_sync(0xffffffffu, t0, 2));
            t1 = fmaxf(t1, __shfl_xor_sync(0xffffffffu, t1, 1));
            t1 = fmaxf(t1, __shfl_xor_sync(0xffffffffu, t1, 2));
            const float mn0 = fmaxf(m0, t0), mn1 = fmaxf(m1, t1);
            const float c0 = exp2a(m0 - mn0), c1 = exp2a(m1 - mn1);
            m0 = mn0; m1 = mn1;
            lacc[0] *= c0; lacc[2] *= c1;
            #pragma unroll
            for (int dt = 0; dt < 8; dt++) {
                o[dt][0] *= c0; o[dt][1] *= c0;
                o[dt][2] *= c1; o[dt][3] *= c1;
            }
            #pragma unroll
            for (int nt = 0; nt < 8; nt++) {
                s[nt][0] = exp2a(s[nt][0] - m0);
                s[nt][1] = exp2a(s[nt][1] - m0);
                s[nt][2] = exp2a(s[nt][2] - m1);
                s[nt][3] = exp2a(s[nt][3] - m1);
            }

            // O += P V ; l += P @ ones (tensor pipe)
            #pragma unroll
            for (int kk2 = 0; kk2 < 4; kk2++) {
                uint32_t pa[4] = {
                    pack2(s[2 * kk2][0],     s[2 * kk2][1]),
                    pack2(s[2 * kk2][2],     s[2 * kk2][3]),
                    pack2(s[2 * kk2 + 1][0], s[2 * kk2 + 1][1]),
                    pack2(s[2 * kk2 + 1][2], s[2 * kk2 + 1][3]) };
                uint32_t onesb[2] = { ONES2, ONES2 };
                mma_f16(lacc, pa, onesb);
                uint32_t bfr[4][4];
                #pragma unroll
                for (int p = 0; p < 4; p++) {
                    int jrow = kk2 * 16 + tr + ((tile & 1) ? 8 : 0);
                    int dcol = 16 * p + ((tile >= 2) ? 8 : 0);
                    ldsm_x4_t(bfr[p], smaddr(&Vs[buf][jrow][dcol]));
                }
                #pragma unroll
                for (int p = 0; p < 4; p++) {
                    mma_f16(o[2 * p],     pa, &bfr[p][0]);
                    mma_f16(o[2 * p + 1], pa, &bfr[p][2]);
                }
            }
        }
    }

    // final normalize + store (fp16); lacc holds full row sums (no reduce needed)
    const float i0 = 1.f / lacc[0], i1 = 1.f / lacc[2];
    __half* y0 = g_y + ((size_t)(b * LL + row0)) * DD + h * DH;
    __half* y1 = y0 + (size_t)8 * DD;
    #pragma unroll
    for (int dt = 0; dt < 8; dt++) {
        *(uint32_t*)(y0 + dt * 8 + 2 * tig) = pack2(o[dt][0] * i0, o[dt][1] * i0);
        *(uint32_t*)(y1 + dt * 8 + 2 * tig) = pack2(o[dt][2] * i1, o[dt][3] * i1);
    }
}

// ---------------------------------------------------------------------------
extern "C" void kernel_launch(void* const* d_in, const int* in_sizes, int n_in,
                              void* d_out, int out_size) {
    const float* x  = (const float*)d_in[0];
    const float* Wq = (const float*)d_in[1];
    const float* Wk = (const float*)d_in[2];
    const float* Wv = (const float*)d_in[3];
    const float* Wo = (const float*)d_in[4];
    float* out = (float*)d_out;

    const int ntot = NX4 + 4 * NW4;
    cvt_all<<<(ntot + 255) / 256, 256>>>(x, Wq, Wk, Wv, Wo);

    dim3 qkvgrid(DD / BN, MM / BM, 3);   // (8, 32, 3)
    gemm_qkv<<<qkvgrid, 256>>>();

    int npairs = MM * (DD / 2);
    rope_kernel<<<(npairs + 255) / 256, 256>>>();

    dim3 agrid(16, BB * HH);
    flash_attn_f16<<<agrid, 256>>>();

    dim3 ggrid(DD / BN, MM / BM);        // (8, 32)
    gemm_out<<<ggrid, 256>>>(out);
}

// round 13
// speedup vs baseline: 11.1853x; 1.0630x over previous
#include <cuda_runtime.h>
#include <cuda_fp16.h>
#include <math_constants.h>
#include <cstdint>

// Problem constants (fixed by the dataset)
#define BB 2
#define LL 2048
#define DD 1024
#define HH 16
#define DH 64
#define MM (BB*LL)   // 4096 rows

// GEMM tiling: CTA 128x128, 4 warps (2x2), warp tile 64x64, BK=32
#define BM 128
#define BN 128
#define BK 32
#define NIT (DD / BK)         // 32
#define LDH 40                // As row stride (halves)
#define LDBH 136              // Bs row stride (halves)

// Attention smem stride (halves)
#define LDKh 72

// Scratch (allocation-free rule: __device__ globals), fp16
__device__ __half g_x16[MM*DD];
__device__ __half g_q[MM*DD];
__device__ __half g_k[MM*DD];
__device__ __half g_v[MM*DD];
__device__ __half g_y[MM*DD];
__device__ __half g_wq[DD*DD];   // [k][n] halves
__device__ __half g_wk[DD*DD];
__device__ __half g_wv[DD*DD];
__device__ __half g_wo[DD*DD];

// ---------------------------------------------------------------------------
__device__ __forceinline__ uint32_t pack2(float lo, float hi) {
    __half2 h = __floats2half2_rn(lo, hi);
    return *reinterpret_cast<uint32_t*>(&h);
}
__device__ __forceinline__ uint32_t smaddr(const void* p) {
    return (uint32_t)__cvta_generic_to_shared(p);
}
__device__ __forceinline__ float exp2a(float x) {
    float r;
    asm("ex2.approx.f32 %0, %1;" : "=f"(r) : "f"(x));
    return r;
}

__device__ __forceinline__ void mma_f16(float* d, const uint32_t* a, const uint32_t* b) {
    asm volatile(
        "mma.sync.aligned.m16n8k16.row.col.f32.f16.f16.f32 "
        "{%0,%1,%2,%3}, {%4,%5,%6,%7}, {%8,%9}, {%0,%1,%2,%3};\n"
        : "+f"(d[0]), "+f"(d[1]), "+f"(d[2]), "+f"(d[3])
        : "r"(a[0]), "r"(a[1]), "r"(a[2]), "r"(a[3]), "r"(b[0]), "r"(b[1]));
}
__device__ __forceinline__ void ldsm_x4(uint32_t* r, uint32_t addr) {
    asm volatile("ldmatrix.sync.aligned.m8n8.x4.shared.b16 {%0,%1,%2,%3}, [%4];"
        : "=r"(r[0]), "=r"(r[1]), "=r"(r[2]), "=r"(r[3]) : "r"(addr));
}
__device__ __forceinline__ void ldsm_x4_t(uint32_t* r, uint32_t addr) {
    asm volatile("ldmatrix.sync.aligned.m8n8.x4.trans.shared.b16 {%0,%1,%2,%3}, [%4];"
        : "=r"(r[0]), "=r"(r[1]), "=r"(r[2]), "=r"(r[3]) : "r"(addr));
}

#define CP16(dst_u32, src_ptr) \
    asm volatile("cp.async.cg.shared.global [%0], [%1], 16;" :: "r"(dst_u32), "l"(src_ptr))
#define CPC()  asm volatile("cp.async.commit_group;" ::: "memory")
#define CPW0() asm volatile("cp.async.wait_group 0;" ::: "memory")

// ---------------------------------------------------------------------------
// Fused f32 -> f16 convert of x + 4 weight matrices (one launch).
// ---------------------------------------------------------------------------
#define NX4 (MM * DD / 4)
#define NW4 (DD * DD / 4)
__global__ __launch_bounds__(256) void cvt_all(const float* __restrict__ x,
                                               const float* __restrict__ Wq,
                                               const float* __restrict__ Wk,
                                               const float* __restrict__ Wv,
                                               const float* __restrict__ Wo) {
    int i = blockIdx.x * blockDim.x + threadIdx.x;   // over NX4 + 4*NW4
    const float* src;
    __half* dst;
    int off;
    if (i < NX4)                { src = x;  dst = g_x16; off = i; }
    else if (i < NX4 + NW4)     { src = Wq; dst = g_wq;  off = i - NX4; }
    else if (i < NX4 + 2*NW4)   { src = Wk; dst = g_wk;  off = i - NX4 - NW4; }
    else if (i < NX4 + 3*NW4)   { src = Wv; dst = g_wv;  off = i - NX4 - 2*NW4; }
    else                        { src = Wo; dst = g_wo;  off = i - NX4 - 3*NW4; }
    float4 v = ((const float4*)src)[off];
    ((uint2*)dst)[off] = make_uint2(pack2(v.x, v.y), pack2(v.z, v.w));
}

// ---------------------------------------------------------------------------
// fp16 mma.sync GEMM: C = scale * A @ Bk, A [m][k], Bk [k][n].
// 128 threads = 4 warps (2m x 2n), warp tile 64x64.
// ---------------------------------------------------------------------------
__device__ __forceinline__ void gemm_body(const __half* __restrict__ A,
                                          const __half* __restrict__ Bk,
                                          void* __restrict__ Cp,
                                          float scale, bool chalf,
                                          int m0, int n0) {
    __shared__ __half As[2][BM][LDH];    // [m][k]
    __shared__ __half Bs[2][BK][LDBH];   // [k][n]

    const int tid  = threadIdx.x;
    const int wid  = tid >> 5;
    const int lane = tid & 31;
    const int grp  = lane >> 2;
    const int tig  = lane & 3;
    const int tile = lane >> 3;
    const int tr   = lane & 7;
    const int wm0  = (wid >> 1) * 64;
    const int wn0  = (wid & 1) * 64;

    float acc[4][8][4];
    #pragma unroll
    for (int mt = 0; mt < 4; mt++)
        #pragma unroll
        for (int nt = 0; nt < 8; nt++)
            #pragma unroll
            for (int r = 0; r < 4; r++) acc[mt][nt][r] = 0.f;

    auto load = [&](int it, int buf) {
        const int k0 = it * BK;
        #pragma unroll
        for (int j = 0; j < 4; j++) {            // A: 512 x 16B chunks
            int c = tid + j * 128;
            int row = c >> 2, q = c & 3;
            CP16(smaddr(&As[buf][row][q * 8]), A + (size_t)(m0 + row) * DD + k0 + q * 8);
        }
        #pragma unroll
        for (int j = 0; j < 4; j++) {            // B: 512 x 16B chunks
            int c = tid + j * 128;
            int row = c >> 4, q = c & 15;
            CP16(smaddr(&Bs[buf][row][q * 8]), Bk + (size_t)(k0 + row) * DD + n0 + q * 8);
        }
    };

    load(0, 0); CPC();

    for (int it = 0; it < NIT; it++) {
        const int buf = it & 1;
        CPW0();
        __syncthreads();
        if (it + 1 < NIT) { load(it + 1, buf ^ 1); CPC(); }

        #pragma unroll
        for (int kd = 0; kd < 2; kd++) {
            const int kb = kd * 16;
            uint32_t a[4][4], bfr[4][4];
            #pragma unroll
            for (int mt = 0; mt < 4; mt++) {
                int mrow = wm0 + mt * 16 + tr + ((tile & 1) ? 8 : 0);
                int kcol = kb + ((tile >= 2) ? 8 : 0);
                ldsm_x4(a[mt], smaddr(&As[buf][mrow][kcol]));
            }
            #pragma unroll
            for (int p = 0; p < 4; p++) {
                int krow = kb + tr + ((tile & 1) ? 8 : 0);
                int ncol = wn0 + 16 * p + ((tile >= 2) ? 8 : 0);
                ldsm_x4_t(bfr[p], smaddr(&Bs[buf][krow][ncol]));
            }
            #pragma unroll
            for (int mt = 0; mt < 4; mt++)
                #pragma unroll
                for (int p = 0; p < 4; p++) {
                    mma_f16(acc[mt][2 * p],     a[mt], &bfr[p][0]);
                    mma_f16(acc[mt][2 * p + 1], a[mt], &bfr[p][2]);
                }
        }
    }

    #pragma unroll
    for (int mt = 0; mt < 4; mt++) {
        #pragma unroll
        for (int nt = 0; nt < 8; nt++) {
            const int m = m0 + wm0 + mt * 16 + grp;
            const int n = n0 + wn0 + nt * 8 + 2 * tig;
            if (chalf) {
                __half* C = (__half*)Cp;
                *(uint32_t*)(C + (size_t)m * DD + n)       = pack2(acc[mt][nt][0] * scale, acc[mt][nt][1] * scale);
                *(uint32_t*)(C + (size_t)(m + 8) * DD + n) = pack2(acc[mt][nt][2] * scale, acc[mt][nt][3] * scale);
            } else {
                float* C = (float*)Cp;
                *(float2*)(C + (size_t)m * DD + n) =
                    make_float2(acc[mt][nt][0] * scale, acc[mt][nt][1] * scale);
                *(float2*)(C + (size_t)(m + 8) * DD + n) =
                    make_float2(acc[mt][nt][2] * scale, acc[mt][nt][3] * scale);
            }
        }
    }
}

// q absorbs 1/sqrt(d) AND log2(e) so softmax runs in exp2 domain (rope is linear).
#define QSCALE 0.04508422002778011f   // log2(e) / 32

__global__ __launch_bounds__(128, 2) void gemm_qkv() {
    const __half* W = (blockIdx.z == 0) ? g_wq : (blockIdx.z == 1) ? g_wk : g_wv;
    __half* C       = (blockIdx.z == 0) ? g_q  : (blockIdx.z == 1) ? g_k  : g_v;
    float scale     = (blockIdx.z == 0) ? QSCALE : 1.0f;
    gemm_body(g_x16, W, C, scale, true, blockIdx.y * BM, blockIdx.x * BN);
}

__global__ __launch_bounds__(128, 2) void gemm_out(float* __restrict__ out) {
    gemm_body(g_y, g_wo, out, 1.0f, false, blockIdx.y * BM, blockIdx.x * BN);
}

// ---------------------------------------------------------------------------
// RoPE on fp16 q and k (in place).
// ---------------------------------------------------------------------------
__global__ __launch_bounds__(256) void rope_kernel() {
    int idx = blockIdx.x * blockDim.x + threadIdx.x;
    if (idx >= MM * (DD / 2)) return;
    int row = idx / (DD / 2);
    int pc  = idx % (DD / 2);
    int pos = row & (LL - 1);
    int hc  = pc & (DH / 2 - 1);

    float inv = exp2f(-(float)hc * 0.41524101186092029f);  // 10000^(-2hc/64)
    float ang = (float)pos * inv;
    float s = sinf(ang), c = cosf(ang);

    __half2* qp = (__half2*)g_q;
    __half2* kp = (__half2*)g_k;
    float2 fq = __half22float2(qp[idx]);
    qp[idx] = __floats2half2_rn(fq.x * c - fq.y * s, fq.y * c + fq.x * s);
    float2 fk = __half22float2(kp[idx]);
    kp[idx] = __floats2half2_rn(fk.x * c - fk.y * s, fk.y * c + fk.x * s);
}

// ---------------------------------------------------------------------------
// fp16 tensor-core flash attention, 128-query CTAs (8 warps x 16 rows).
// exp2-domain softmax; row-sums via ones-MMA; warp-voted rescale skip.
// ---------------------------------------------------------------------------
#define ONES2 0x3C003C00u   // half2(1.0, 1.0)

__global__ __launch_bounds__(256, 2) void flash_attn_f16() {
    __shared__ __half Ks[2][64][LDKh];   // [key j][d]
    __shared__ __half Vs[2][64][LDKh];   // [key j][d]

    const int qt  = (int)gridDim.x - 1 - blockIdx.x;   // heavy tiles first
    const int bh  = blockIdx.y;
    const int b   = bh >> 4;
    const int h   = bh & 15;
    const int tid = threadIdx.x;
    const int wid = tid >> 5;
    const int lane = tid & 31;
    const int grp = lane >> 2;
    const int tig = lane & 3;
    const int tile = lane >> 3;
    const int tr   = lane & 7;
    const int q0  = qt * 128;
    const int wrow = q0 + wid * 16;          // warp's first row
    const int row0 = wrow + grp;             // rows row0 and row0+8
    const int kt_max = (q0 + 127) >> 6;      // inclusive

    auto loadKV = [&](int kt, int buf) {
        const int kb = kt * 64;
        #pragma unroll
        for (int j = 0; j < 2; j++) {
            int c = tid + j * 256;
            int row = c >> 3, q = c & 7;
            size_t off = (size_t)(b * LL + kb + row) * DD + h * DH + q * 8;
            CP16(smaddr(&Ks[buf][row][q * 8]), g_k + off);
            CP16(smaddr(&Vs[buf][row][q * 8]), g_v + off);
        }
    };

    // Q fragments straight from gmem (fp16 pairs)
    uint32_t qa[4][4];
    {
        const __half* qr0 = g_q + ((size_t)(b * LL + row0)) * DD + h * DH;
        const __half* qr1 = qr0 + (size_t)8 * DD;
        #pragma unroll
        for (int kd = 0; kd < 4; kd++) {
            qa[kd][0] = *(const uint32_t*)(qr0 + kd * 16 + 2 * tig);
            qa[kd][1] = *(const uint32_t*)(qr1 + kd * 16 + 2 * tig);
            qa[kd][2] = *(const uint32_t*)(qr0 + kd * 16 + 2 * tig + 8);
            qa[kd][3] = *(const uint32_t*)(qr1 + kd * 16 + 2 * tig + 8);
        }
    }

    float o[8][4];
    #pragma unroll
    for (int dt = 0; dt < 8; dt++)
        #pragma unroll
        for (int r = 0; r < 4; r++) o[dt][r] = 0.f;
    float lacc[4] = {0.f, 0.f, 0.f, 0.f};    // row sums via ones-MMA ([0],[2] used)
    float m0 = -CUDART_INF_F, m1 = -CUDART_INF_F;

    loadKV(0, 0); CPC();

    for (int kt0 = 0; kt0 <= kt_max; kt0++) {
        const int kb = kt0 * 64;
        const int buf = kt0 & 1;
        CPW0();
        __syncthreads();
        if (kt0 < kt_max) { loadKV(kt0 + 1, buf ^ 1); CPC(); }

        if (kb <= wrow + 15) {
            // S = Q K^T  (logits already in log2 domain via QSCALE)
            float s[8][4];
            #pragma unroll
            for (int nt = 0; nt < 8; nt++)
                #pragma unroll
                for (int r = 0; r < 4; r++) s[nt][r] = 0.f;
            #pragma unroll
            for (int kd = 0; kd < 4; kd++) {
                uint32_t bfr[4][4];
                #pragma unroll
                for (int p = 0; p < 4; p++) {
                    int nrow = 16 * p + tr + ((tile >= 2) ? 8 : 0);
                    int kcol = kd * 16 + ((tile & 1) ? 8 : 0);
                    ldsm_x4(bfr[p], smaddr(&Ks[buf][nrow][kcol]));
                }
                #pragma unroll
                for (int p = 0; p < 4; p++) {
                    mma_f16(s[2 * p],     qa[kd], &bfr[p][0]);
                    mma_f16(s[2 * p + 1], qa[kd], &bfr[p][2]);
                }
            }

            // causal mask (tiles overlapping this warp's diagonal)
            if (kb + 63 > wrow) {
                #pragma unroll
                for (int nt = 0; nt < 8; nt++) {
                    const int j = kb + nt * 8 + 2 * tig;
                    if (j     > row0)     s[nt][0] = -CUDART_INF_F;
                    if (j + 1 > row0)     s[nt][1] = -CUDART_INF_F;
                    if (j     > row0 + 8) s[nt][2] = -CUDART_INF_F;
                    if (j + 1 > row0 + 8) s[nt][3] = -CUDART_INF_F;
                }
            }

            // online softmax (exp2 domain)
            float t0 = s[0][0], t1 = s[0][2];
            #pragma unroll
            for (int nt = 0; nt < 8; nt++) {
                t0 = fmaxf(t0, fmaxf(s[nt][0], s[nt][1]));
                t1 = fmaxf(t1, fmaxf(s[nt][2], s[nt][3]));
            }
            t0 = fmaxf(t0, __shfl_xor_sync(0xffffffffu, t0, 1));
            t0 = fmaxf(t0, __shfl_xor_sync(0xffffffffu, t0, 2));
            t1 = fmaxf(t1, __shfl_xor_sync(0xffffffffu, t1, 1));
            t1 = fmaxf(t1, __shfl_xor_sync(0xffffffffu, t1, 2));
            const float mn0 = fmaxf(m0, t0), mn1 = fmaxf(m1, t1);
            // warp-voted rescale skip (exact): if no lane's max moved, o/lacc stay valid
            bool moved = (mn0 > m0) || (mn1 > m1);
            if (__any_sync(0xffffffffu, moved)) {
                const float c0 = exp2a(m0 - mn0), c1 = exp2a(m1 - mn1);
                lacc[0] *= c0; lacc[2] *= c1;
                #pragma unroll
                for (int dt = 0; dt < 8; dt++) {
                    o[dt][0] *= c0; o[dt][1] *= c0;
                    o[dt][2] *= c1; o[dt][3] *= c1;
                }
                m0 = mn0; m1 = mn1;
            }
            #pragma unroll
            for (int nt = 0; nt < 8; nt++) {
                s[nt][0] = exp2a(s[nt][0] - m0);
                s[nt][1] = exp2a(s[nt][1] - m0);
                s[nt][2] = exp2a(s[nt][2] - m1);
                s[nt][3] = exp2a(s[nt][3] - m1);
            }

            // O += P V ; l += P @ ones (tensor pipe)
            #pragma unroll
            for (int kk2 = 0; kk2 < 4; kk2++) {
                uint32_t pa[4] = {
                    pack2(s[2 * kk2][0],     s[2 * kk2][1]),
                    pack2(s[2 * kk2][2],     s[2 * kk2][3]),
                    pack2(s[2 * kk2 + 1][0], s[2 * kk2 + 1][1]),
                    pack2(s[2 * kk2 + 1][2], s[2 * kk2 + 1][3]) };
                uint32_t onesb[2] = { ONES2, ONES2 };
                mma_f16(lacc, pa, onesb);
                uint32_t bfr[4][4];
                #pragma unroll
                for (int p = 0; p < 4; p++) {
                    int jrow = kk2 * 16 + tr + ((tile & 1) ? 8 : 0);
                    int dcol = 16 * p + ((tile >= 2) ? 8 : 0);
                    ldsm_x4_t(bfr[p], smaddr(&Vs[buf][jrow][dcol]));
                }
                #pragma unroll
                for (int p = 0; p < 4; p++) {
                    mma_f16(o[2 * p],     pa, &bfr[p][0]);
                    mma_f16(o[2 * p + 1], pa, &bfr[p][2]);
                }
            }
        }
    }

    // final normalize + store (fp16); lacc holds full row sums (no reduce needed)
    const float i0 = 1.f / lacc[0], i1 = 1.f / lacc[2];
    __half* y0 = g_y + ((size_t)(b * LL + row0)) * DD + h * DH;
    __half* y1 = y0 + (size_t)8 * DD;
    #pragma unroll
    for (int dt = 0; dt < 8; dt++) {
        *(uint32_t*)(y0 + dt * 8 + 2 * tig) = pack2(o[dt][0] * i0, o[dt][1] * i0);
        *(uint32_t*)(y1 + dt * 8 + 2 * tig) = pack2(o[dt][2] * i1, o[dt][3] * i1);
    }
}

// ---------------------------------------------------------------------------
extern "C" void kernel_launch(void* const* d_in, const int* in_sizes, int n_in,
                              void* d_out, int out_size) {
    const float* x  = (const float*)d_in[0];
    const float* Wq = (const float*)d_in[1];
    const float* Wk = (const float*)d_in[2];
    const float* Wv = (const float*)d_in[3];
    const float* Wo = (const float*)d_in[4];
    float* out = (float*)d_out;

    const int ntot = NX4 + 4 * NW4;
    cvt_all<<<(ntot + 255) / 256, 256>>>(x, Wq, Wk, Wv, Wo);

    dim3 qkvgrid(DD / BN, MM / BM, 3);   // (8, 32, 3)
    gemm_qkv<<<qkvgrid, 128>>>();

    int npairs = MM * (DD / 2);
    rope_kernel<<<(npairs + 255) / 256, 256>>>();

    dim3 agrid(16, BB * HH);
    flash_attn_f16<<<agrid, 256>>>();

    dim3 ggrid(DD / BN, MM / BM);        // (8, 32)
    gemm_out<<<ggrid, 128>>>(out);
}

// round 14
// speedup vs baseline: 11.5641x; 1.0339x over previous
#include <cuda_runtime.h>
#include <cuda_fp16.h>
#include <math_constants.h>
#include <cstdint>

// Problem constants (fixed by the dataset)
#define BB 2
#define LL 2048
#define DD 1024
#define HH 16
#define DH 64
#define MM (BB*LL)   // 4096 rows

// GEMM tiling: CTA 128x128, 4 warps (2x2), warp tile 64x64, BK=32
#define BM 128
#define BN 128
#define BK 32
#define NIT (DD / BK)         // 32
#define LDH 40                // As row stride (halves)
#define LDBH 136              // Bs row stride (halves)

// Attention smem stride (halves)
#define LDKh 72

// Scratch (allocation-free rule: __device__ globals), fp16
__device__ __half g_x16[MM*DD];
__device__ __half g_q[MM*DD];
__device__ __half g_k[MM*DD];
__device__ __half g_v[MM*DD];
__device__ __half g_y[MM*DD];
__device__ __half g_wq[DD*DD];   // [k][n] halves
__device__ __half g_wk[DD*DD];
__device__ __half g_wv[DD*DD];
__device__ __half g_wo[DD*DD];

// ---------------------------------------------------------------------------
__device__ __forceinline__ uint32_t pack2(float lo, float hi) {
    __half2 h = __floats2half2_rn(lo, hi);
    return *reinterpret_cast<uint32_t*>(&h);
}
__device__ __forceinline__ uint32_t smaddr(const void* p) {
    return (uint32_t)__cvta_generic_to_shared(p);
}
__device__ __forceinline__ float exp2a(float x) {
    float r;
    asm("ex2.approx.f32 %0, %1;" : "=f"(r) : "f"(x));
    return r;
}

__device__ __forceinline__ void mma_f16(float* d, const uint32_t* a, const uint32_t* b) {
    asm volatile(
        "mma.sync.aligned.m16n8k16.row.col.f32.f16.f16.f32 "
        "{%0,%1,%2,%3}, {%4,%5,%6,%7}, {%8,%9}, {%0,%1,%2,%3};\n"
        : "+f"(d[0]), "+f"(d[1]), "+f"(d[2]), "+f"(d[3])
        : "r"(a[0]), "r"(a[1]), "r"(a[2]), "r"(a[3]), "r"(b[0]), "r"(b[1]));
}
__device__ __forceinline__ void ldsm_x4(uint32_t* r, uint32_t addr) {
    asm volatile("ldmatrix.sync.aligned.m8n8.x4.shared.b16 {%0,%1,%2,%3}, [%4];"
        : "=r"(r[0]), "=r"(r[1]), "=r"(r[2]), "=r"(r[3]) : "r"(addr));
}
__device__ __forceinline__ void ldsm_x4_t(uint32_t* r, uint32_t addr) {
    asm volatile("ldmatrix.sync.aligned.m8n8.x4.trans.shared.b16 {%0,%1,%2,%3}, [%4];"
        : "=r"(r[0]), "=r"(r[1]), "=r"(r[2]), "=r"(r[3]) : "r"(addr));
}

#define CP16(dst_u32, src_ptr) \
    asm volatile("cp.async.cg.shared.global [%0], [%1], 16;" :: "r"(dst_u32), "l"(src_ptr))
#define CPC()  asm volatile("cp.async.commit_group;" ::: "memory")
#define CPW0() asm volatile("cp.async.wait_group 0;" ::: "memory")

// ---------------------------------------------------------------------------
// Fused f32 -> f16 convert of x + 4 weight matrices (one launch).
// ---------------------------------------------------------------------------
#define NX4 (MM * DD / 4)
#define NW4 (DD * DD / 4)
__global__ __launch_bounds__(256) void cvt_all(const float* __restrict__ x,
                                               const float* __restrict__ Wq,
                                               const float* __restrict__ Wk,
                                               const float* __restrict__ Wv,
                                               const float* __restrict__ Wo) {
    int i = blockIdx.x * blockDim.x + threadIdx.x;   // over NX4 + 4*NW4
    const float* src;
    __half* dst;
    int off;
    if (i < NX4)                { src = x;  dst = g_x16; off = i; }
    else if (i < NX4 + NW4)     { src = Wq; dst = g_wq;  off = i - NX4; }
    else if (i < NX4 + 2*NW4)   { src = Wk; dst = g_wk;  off = i - NX4 - NW4; }
    else if (i < NX4 + 3*NW4)   { src = Wv; dst = g_wv;  off = i - NX4 - 2*NW4; }
    else                        { src = Wo; dst = g_wo;  off = i - NX4 - 3*NW4; }
    float4 v = ((const float4*)src)[off];
    ((uint2*)dst)[off] = make_uint2(pack2(v.x, v.y), pack2(v.z, v.w));
}

// ---------------------------------------------------------------------------
// fp16 mma.sync GEMM: C = scale * A @ Bk, A [m][k], Bk [k][n].
// 128 threads = 4 warps (2m x 2n), warp tile 64x64.
// dorope: apply RoPE rotation in the epilogue (q/k outputs, fp16).
// ---------------------------------------------------------------------------
__device__ __forceinline__ void gemm_body(const __half* __restrict__ A,
                                          const __half* __restrict__ Bk,
                                          void* __restrict__ Cp,
                                          float scale, bool chalf, bool dorope,
                                          int m0, int n0) {
    __shared__ __half As[2][BM][LDH];    // [m][k]
    __shared__ __half Bs[2][BK][LDBH];   // [k][n]

    const int tid  = threadIdx.x;
    const int wid  = tid >> 5;
    const int lane = tid & 31;
    const int grp  = lane >> 2;
    const int tig  = lane & 3;
    const int tile = lane >> 3;
    const int tr   = lane & 7;
    const int wm0  = (wid >> 1) * 64;
    const int wn0  = (wid & 1) * 64;

    float acc[4][8][4];
    #pragma unroll
    for (int mt = 0; mt < 4; mt++)
        #pragma unroll
        for (int nt = 0; nt < 8; nt++)
            #pragma unroll
            for (int r = 0; r < 4; r++) acc[mt][nt][r] = 0.f;

    auto load = [&](int it, int buf) {
        const int k0 = it * BK;
        #pragma unroll
        for (int j = 0; j < 4; j++) {            // A: 512 x 16B chunks
            int c = tid + j * 128;
            int row = c >> 2, q = c & 3;
            CP16(smaddr(&As[buf][row][q * 8]), A + (size_t)(m0 + row) * DD + k0 + q * 8);
        }
        #pragma unroll
        for (int j = 0; j < 4; j++) {            // B: 512 x 16B chunks
            int c = tid + j * 128;
            int row = c >> 4, q = c & 15;
            CP16(smaddr(&Bs[buf][row][q * 8]), Bk + (size_t)(k0 + row) * DD + n0 + q * 8);
        }
    };

    load(0, 0); CPC();

    for (int it = 0; it < NIT; it++) {
        const int buf = it & 1;
        CPW0();
        __syncthreads();
        if (it + 1 < NIT) { load(it + 1, buf ^ 1); CPC(); }

        #pragma unroll
        for (int kd = 0; kd < 2; kd++) {
            const int kb = kd * 16;
            uint32_t a[4][4], bfr[4][4];
            #pragma unroll
            for (int mt = 0; mt < 4; mt++) {
                int mrow = wm0 + mt * 16 + tr + ((tile & 1) ? 8 : 0);
                int kcol = kb + ((tile >= 2) ? 8 : 0);
                ldsm_x4(a[mt], smaddr(&As[buf][mrow][kcol]));
            }
            #pragma unroll
            for (int p = 0; p < 4; p++) {
                int krow = kb + tr + ((tile & 1) ? 8 : 0);
                int ncol = wn0 + 16 * p + ((tile >= 2) ? 8 : 0);
                ldsm_x4_t(bfr[p], smaddr(&Bs[buf][krow][ncol]));
            }
            #pragma unroll
            for (int mt = 0; mt < 4; mt++)
                #pragma unroll
                for (int p = 0; p < 4; p++) {
                    mma_f16(acc[mt][2 * p],     a[mt], &bfr[p][0]);
                    mma_f16(acc[mt][2 * p + 1], a[mt], &bfr[p][2]);
                }
        }
    }

    if (dorope) {
        // RoPE in epilogue. Thread holds rows (m, m+8), cols (n, n+1), n even.
        // pos(mt) = base + 16*mt (no 2048-wrap inside a 128-row tile);
        // hi row = +8. Angle chain: 2 accurate sincos per nt, rest exact rotations.
        __half* C = (__half*)Cp;
        const int base = (m0 + wm0 + grp) & (LL - 1);
        #pragma unroll
        for (int nt = 0; nt < 8; nt++) {
            const int n = n0 + wn0 + nt * 8 + 2 * tig;
            const int hc = (n & (DH - 1)) >> 1;
            float inv = exp2f(-(float)hc * 0.41524101186092029f);  // 10000^(-2hc/64)
            float sb, cb, s8, c8;
            sincosf((float)base * inv, &sb, &cb);
            sincosf(8.0f * inv, &s8, &c8);
            const float s16 = 2.f * s8 * c8;
            const float c16 = 1.f - 2.f * s8 * s8;
            float sl = sb, cl = cb;
            #pragma unroll
            for (int mt = 0; mt < 4; mt++) {
                const float sh = sl * c8 + cl * s8;
                const float ch = cl * c8 - sl * s8;
                const float x0 = acc[mt][nt][0] * scale, y0 = acc[mt][nt][1] * scale;
                const float x1 = acc[mt][nt][2] * scale, y1 = acc[mt][nt][3] * scale;
                const int m = m0 + wm0 + mt * 16 + grp;
                *(uint32_t*)(C + (size_t)m * DD + n) =
                    pack2(x0 * cl - y0 * sl, y0 * cl + x0 * sl);
                *(uint32_t*)(C + (size_t)(m + 8) * DD + n) =
                    pack2(x1 * ch - y1 * sh, y1 * ch + x1 * sh);
                const float sn = sl * c16 + cl * s16;
                const float cn = cl * c16 - sl * s16;
                sl = sn; cl = cn;
            }
        }
    } else {
        #pragma unroll
        for (int mt = 0; mt < 4; mt++) {
            #pragma unroll
            for (int nt = 0; nt < 8; nt++) {
                const int m = m0 + wm0 + mt * 16 + grp;
                const int n = n0 + wn0 + nt * 8 + 2 * tig;
                if (chalf) {
                    __half* C = (__half*)Cp;
                    *(uint32_t*)(C + (size_t)m * DD + n)       = pack2(acc[mt][nt][0] * scale, acc[mt][nt][1] * scale);
                    *(uint32_t*)(C + (size_t)(m + 8) * DD + n) = pack2(acc[mt][nt][2] * scale, acc[mt][nt][3] * scale);
                } else {
                    float* C = (float*)Cp;
                    *(float2*)(C + (size_t)m * DD + n) =
                        make_float2(acc[mt][nt][0] * scale, acc[mt][nt][1] * scale);
                    *(float2*)(C + (size_t)(m + 8) * DD + n) =
                        make_float2(acc[mt][nt][2] * scale, acc[mt][nt][3] * scale);
                }
            }
        }
    }
}

// q absorbs 1/sqrt(d) AND log2(e) so softmax runs in exp2 domain (rope is linear).
#define QSCALE 0.04508422002778011f   // log2(e) / 32

__global__ __launch_bounds__(128, 2) void gemm_qkv() {
    const __half* W = (blockIdx.z == 0) ? g_wq : (blockIdx.z == 1) ? g_wk : g_wv;
    __half* C       = (blockIdx.z == 0) ? g_q  : (blockIdx.z == 1) ? g_k  : g_v;
    float scale     = (blockIdx.z == 0) ? QSCALE : 1.0f;
    bool dorope     = (blockIdx.z != 2);
    gemm_body(g_x16, W, C, scale, true, dorope, blockIdx.y * BM, blockIdx.x * BN);
}

__global__ __launch_bounds__(128, 2) void gemm_out(float* __restrict__ out) {
    gemm_body(g_y, g_wo, out, 1.0f, false, false, blockIdx.y * BM, blockIdx.x * BN);
}

// ---------------------------------------------------------------------------
// fp16 tensor-core flash attention, 128-query CTAs (8 warps x 16 rows).
// exp2-domain softmax; row-sums via ones-MMA.
// ---------------------------------------------------------------------------
#define ONES2 0x3C003C00u   // half2(1.0, 1.0)

__global__ __launch_bounds__(256, 2) void flash_attn_f16() {
    __shared__ __half Ks[2][64][LDKh];   // [key j][d]
    __shared__ __half Vs[2][64][LDKh];   // [key j][d]

    const int qt  = (int)gridDim.x - 1 - blockIdx.x;   // heavy tiles first
    const int bh  = blockIdx.y;
    const int b   = bh >> 4;
    const int h   = bh & 15;
    const int tid = threadIdx.x;
    const int wid = tid >> 5;
    const int lane = tid & 31;
    const int grp = lane >> 2;
    const int tig = lane & 3;
    const int tile = lane >> 3;
    const int tr   = lane & 7;
    const int q0  = qt * 128;
    const int wrow = q0 + wid * 16;          // warp's first row
    const int row0 = wrow + grp;             // rows row0 and row0+8
    const int kt_max = (q0 + 127) >> 6;      // inclusive

    auto loadKV = [&](int kt, int buf) {
        const int kb = kt * 64;
        #pragma unroll
        for (int j = 0; j < 2; j++) {
            int c = tid + j * 256;
            int row = c >> 3, q = c & 7;
            size_t off = (size_t)(b * LL + kb + row) * DD + h * DH + q * 8;
            CP16(smaddr(&Ks[buf][row][q * 8]), g_k + off);
            CP16(smaddr(&Vs[buf][row][q * 8]), g_v + off);
        }
    };

    // Q fragments straight from gmem (fp16 pairs)
    uint32_t qa[4][4];
    {
        const __half* qr0 = g_q + ((size_t)(b * LL + row0)) * DD + h * DH;
        const __half* qr1 = qr0 + (size_t)8 * DD;
        #pragma unroll
        for (int kd = 0; kd < 4; kd++) {
            qa[kd][0] = *(const uint32_t*)(qr0 + kd * 16 + 2 * tig);
            qa[kd][1] = *(const uint32_t*)(qr1 + kd * 16 + 2 * tig);
            qa[kd][2] = *(const uint32_t*)(qr0 + kd * 16 + 2 * tig + 8);
            qa[kd][3] = *(const uint32_t*)(qr1 + kd * 16 + 2 * tig + 8);
        }
    }

    float o[8][4];
    #pragma unroll
    for (int dt = 0; dt < 8; dt++)
        #pragma unroll
        for (int r = 0; r < 4; r++) o[dt][r] = 0.f;
    float lacc[4] = {0.f, 0.f, 0.f, 0.f};    // row sums via ones-MMA ([0],[2] used)
    float m0 = -CUDART_INF_F, m1 = -CUDART_INF_F;

    loadKV(0, 0); CPC();

    for (int kt0 = 0; kt0 <= kt_max; kt0++) {
        const int kb = kt0 * 64;
        const int buf = kt0 & 1;
        CPW0();
        __syncthreads();
        if (kt0 < kt_max) { loadKV(kt0 + 1, buf ^ 1); CPC(); }

        if (kb <= wrow + 15) {
            // S = Q K^T  (logits already in log2 domain via QSCALE)
            float s[8][4];
            #pragma unroll
            for (int nt = 0; nt < 8; nt++)
                #pragma unroll
                for (int r = 0; r < 4; r++) s[nt][r] = 0.f;
            #pragma unroll
            for (int kd = 0; kd < 4; kd++) {
                uint32_t bfr[4][4];
                #pragma unroll
                for (int p = 0; p < 4; p++) {
                    int nrow = 16 * p + tr + ((tile >= 2) ? 8 : 0);
                    int kcol = kd * 16 + ((tile & 1) ? 8 : 0);
                    ldsm_x4(bfr[p], smaddr(&Ks[buf][nrow][kcol]));
                }
                #pragma unroll
                for (int p = 0; p < 4; p++) {
                    mma_f16(s[2 * p],     qa[kd], &bfr[p][0]);
                    mma_f16(s[2 * p + 1], qa[kd], &bfr[p][2]);
                }
            }

            // causal mask (tiles overlapping this warp's diagonal)
            if (kb + 63 > wrow) {
                #pragma unroll
                for (int nt = 0; nt < 8; nt++) {
                    const int j = kb + nt * 8 + 2 * tig;
                    if (j     > row0)     s[nt][0] = -CUDART_INF_F;
                    if (j + 1 > row0)     s[nt][1] = -CUDART_INF_F;
                    if (j     > row0 + 8) s[nt][2] = -CUDART_INF_F;
                    if (j + 1 > row0 + 8) s[nt][3] = -CUDART_INF_F;
                }
            }

            // online softmax (exp2 domain)
            float t0 = s[0][0], t1 = s[0][2];
            #pragma unroll
            for (int nt = 0; nt < 8; nt++) {
                t0 = fmaxf(t0, fmaxf(s[nt][0], s[nt][1]));
                t1 = fmaxf(t1, fmaxf(s[nt][2], s[nt][3]));
            }
            t0 = fmaxf(t0, __shfl_xor_sync(0xffffffffu, t0, 1));
            t0 = fmaxf(t0, __shfl_xor_sync(0xffffffffu, t0, 2));
            t1 = fmaxf(t1, __shfl_xor_sync(0xffffffffu, t1, 1));
            t1 = fmaxf(t1, __shfl_xor_sync(0xffffffffu, t1, 2));
            const float mn0 = fmaxf(m0, t0), mn1 = fmaxf(m1, t1);
            const float c0 = exp2a(m0 - mn0), c1 = exp2a(m1 - mn1);
            m0 = mn0; m1 = mn1;
            lacc[0] *= c0; lacc[2] *= c1;
            #pragma unroll
            for (int dt = 0; dt < 8; dt++) {
                o[dt][0] *= c0; o[dt][1] *= c0;
                o[dt][2] *= c1; o[dt][3] *= c1;
            }
            #pragma unroll
            for (int nt = 0; nt < 8; nt++) {
                s[nt][0] = exp2a(s[nt][0] - m0);
                s[nt][1] = exp2a(s[nt][1] - m0);
                s[nt][2] = exp2a(s[nt][2] - m1);
                s[nt][3] = exp2a(s[nt][3] - m1);
            }

            // O += P V ; l += P @ ones (tensor pipe)
            #pragma unroll
            for (int kk2 = 0; kk2 < 4; kk2++) {
                uint32_t pa[4] = {
                    pack2(s[2 * kk2][0],     s[2 * kk2][1]),
                    pack2(s[2 * kk2][2],     s[2 * kk2][3]),
                    pack2(s[2 * kk2 + 1][0], s[2 * kk2 + 1][1]),
                    pack2(s[2 * kk2 + 1][2], s[2 * kk2 + 1][3]) };
                uint32_t onesb[2] = { ONES2, ONES2 };
                mma_f16(lacc, pa, onesb);
                uint32_t bfr[4][4];
                #pragma unroll
                for (int p = 0; p < 4; p++) {
                    int jrow = kk2 * 16 + tr + ((tile & 1) ? 8 : 0);
                    int dcol = 16 * p + ((tile >= 2) ? 8 : 0);
                    ldsm_x4_t(bfr[p], smaddr(&Vs[buf][jrow][dcol]));
                }
                #pragma unroll
                for (int p = 0; p < 4; p++) {
                    mma_f16(o[2 * p],     pa, &bfr[p][0]);
                    mma_f16(o[2 * p + 1], pa, &bfr[p][2]);
                }
            }
        }
    }

    // final normalize + store (fp16); lacc holds full row sums (no reduce needed)
    const float i0 = 1.f / lacc[0], i1 = 1.f / lacc[2];
    __half* y0 = g_y + ((size_t)(b * LL + row0)) * DD + h * DH;
    __half* y1 = y0 + (size_t)8 * DD;
    #pragma unroll
    for (int dt = 0; dt < 8; dt++) {
        *(uint32_t*)(y0 + dt * 8 + 2 * tig) = pack2(o[dt][0] * i0, o[dt][1] * i0);
        *(uint32_t*)(y1 + dt * 8 + 2 * tig) = pack2(o[dt][2] * i1, o[dt][3] * i1);
    }
}

// ---------------------------------------------------------------------------
extern "C" void kernel_launch(void* const* d_in, const int* in_sizes, int n_in,
                              void* d_out, int out_size) {
    const float* x  = (const float*)d_in[0];
    const float* Wq = (const float*)d_in[1];
    const float* Wk = (const float*)d_in[2];
    const float* Wv = (const float*)d_in[3];
    const float* Wo = (const float*)d_in[4];
    float* out = (float*)d_out;

    const int ntot = NX4 + 4 * NW4;
    cvt_all<<<(ntot + 255) / 256, 256>>>(x, Wq, Wk, Wv, Wo);

    dim3 qkvgrid(DD / BN, MM / BM, 3);   // (8, 32, 3)
    gemm_qkv<<<qkvgrid, 128>>>();

    dim3 agrid(16, BB * HH);
    flash_attn_f16<<<agrid, 256>>>();

    dim3 ggrid(DD / BN, MM / BM);        // (8, 32)
    gemm_out<<<ggrid, 128>>>(out);
}

// round 15
// speedup vs baseline: 11.6921x; 1.0111x over previous
#include <cuda_runtime.h>
#include <cuda_fp16.h>
#include <math_constants.h>
#include <cstdint>

// Problem constants (fixed by the dataset)
#define BB 2
#define LL 2048
#define DD 1024
#define HH 16
#define DH 64
#define MM (BB*LL)   // 4096 rows

// GEMM tiling: CTA 128x128, 4 warps (2x2), warp tile 64x64, BK=32
#define BM 128
#define BN 128
#define BK 32
#define NIT (DD / BK)         // 32
#define LDH 40                // As row stride (halves)
#define LDBH 136              // Bs row stride (halves)

// Attention smem stride (halves)
#define LDKh 72

// Scratch (allocation-free rule: __device__ globals), fp16
__device__ __half g_x16[MM*DD];
__device__ __half g_q[MM*DD];
__device__ __half g_k[MM*DD];
__device__ __half g_v[MM*DD];
__device__ __half g_y[MM*DD];
__device__ __half g_wq[DD*DD];   // [k][n] halves
__device__ __half g_wk[DD*DD];
__device__ __half g_wv[DD*DD];
__device__ __half g_wo[DD*DD];

// ---------------------------------------------------------------------------
__device__ __forceinline__ uint32_t pack2(float lo, float hi) {
    __half2 h = __floats2half2_rn(lo, hi);
    return *reinterpret_cast<uint32_t*>(&h);
}
__device__ __forceinline__ uint32_t smaddr(const void* p) {
    return (uint32_t)__cvta_generic_to_shared(p);
}
__device__ __forceinline__ float exp2a(float x) {
    float r;
    asm("ex2.approx.f32 %0, %1;" : "=f"(r) : "f"(x));
    return r;
}
// packed fp16 exp2 of (lo, hi): output IS an fp16x2 MMA fragment word
__device__ __forceinline__ uint32_t exp2h2(float lo, float hi) {
    uint32_t h = pack2(lo, hi);
    uint32_t r;
    asm("ex2.approx.f16x2 %0, %1;" : "=r"(r) : "r"(h));
    return r;
}

__device__ __forceinline__ void mma_f16(float* d, const uint32_t* a, const uint32_t* b) {
    asm volatile(
        "mma.sync.aligned.m16n8k16.row.col.f32.f16.f16.f32 "
        "{%0,%1,%2,%3}, {%4,%5,%6,%7}, {%8,%9}, {%0,%1,%2,%3};\n"
        : "+f"(d[0]), "+f"(d[1]), "+f"(d[2]), "+f"(d[3])
        : "r"(a[0]), "r"(a[1]), "r"(a[2]), "r"(a[3]), "r"(b[0]), "r"(b[1]));
}
__device__ __forceinline__ void ldsm_x4(uint32_t* r, uint32_t addr) {
    asm volatile("ldmatrix.sync.aligned.m8n8.x4.shared.b16 {%0,%1,%2,%3}, [%4];"
        : "=r"(r[0]), "=r"(r[1]), "=r"(r[2]), "=r"(r[3]) : "r"(addr));
}
__device__ __forceinline__ void ldsm_x4_t(uint32_t* r, uint32_t addr) {
    asm volatile("ldmatrix.sync.aligned.m8n8.x4.trans.shared.b16 {%0,%1,%2,%3}, [%4];"
        : "=r"(r[0]), "=r"(r[1]), "=r"(r[2]), "=r"(r[3]) : "r"(addr));
}

#define CP16(dst_u32, src_ptr) \
    asm volatile("cp.async.cg.shared.global [%0], [%1], 16;" :: "r"(dst_u32), "l"(src_ptr))
#define CPC()  asm volatile("cp.async.commit_group;" ::: "memory")
#define CPW0() asm volatile("cp.async.wait_group 0;" ::: "memory")

// ---------------------------------------------------------------------------
// Fused f32 -> f16 convert of x + 4 weight matrices (one launch).
// ---------------------------------------------------------------------------
#define NX4 (MM * DD / 4)
#define NW4 (DD * DD / 4)
__global__ __launch_bounds__(256) void cvt_all(const float* __restrict__ x,
                                               const float* __restrict__ Wq,
                                               const float* __restrict__ Wk,
                                               const float* __restrict__ Wv,
                                               const float* __restrict__ Wo) {
    int i = blockIdx.x * blockDim.x + threadIdx.x;   // over NX4 + 4*NW4
    const float* src;
    __half* dst;
    int off;
    if (i < NX4)                { src = x;  dst = g_x16; off = i; }
    else if (i < NX4 + NW4)     { src = Wq; dst = g_wq;  off = i - NX4; }
    else if (i < NX4 + 2*NW4)   { src = Wk; dst = g_wk;  off = i - NX4 - NW4; }
    else if (i < NX4 + 3*NW4)   { src = Wv; dst = g_wv;  off = i - NX4 - 2*NW4; }
    else                        { src = Wo; dst = g_wo;  off = i - NX4 - 3*NW4; }
    float4 v = ((const float4*)src)[off];
    ((uint2*)dst)[off] = make_uint2(pack2(v.x, v.y), pack2(v.z, v.w));
}

// ---------------------------------------------------------------------------
// fp16 mma.sync GEMM: C = scale * A @ Bk, A [m][k], Bk [k][n].
// 128 threads = 4 warps (2m x 2n), warp tile 64x64.
// dorope: apply RoPE rotation in the epilogue (q/k outputs, fp16).
// ---------------------------------------------------------------------------
__device__ __forceinline__ void gemm_body(const __half* __restrict__ A,
                                          const __half* __restrict__ Bk,
                                          void* __restrict__ Cp,
                                          float scale, bool chalf, bool dorope,
                                          int m0, int n0) {
    __shared__ __half As[2][BM][LDH];    // [m][k]
    __shared__ __half Bs[2][BK][LDBH];   // [k][n]

    const int tid  = threadIdx.x;
    const int wid  = tid >> 5;
    const int lane = tid & 31;
    const int grp  = lane >> 2;
    const int tig  = lane & 3;
    const int tile = lane >> 3;
    const int tr   = lane & 7;
    const int wm0  = (wid >> 1) * 64;
    const int wn0  = (wid & 1) * 64;

    float acc[4][8][4];
    #pragma unroll
    for (int mt = 0; mt < 4; mt++)
        #pragma unroll
        for (int nt = 0; nt < 8; nt++)
            #pragma unroll
            for (int r = 0; r < 4; r++) acc[mt][nt][r] = 0.f;

    auto load = [&](int it, int buf) {
        const int k0 = it * BK;
        #pragma unroll
        for (int j = 0; j < 4; j++) {            // A: 512 x 16B chunks
            int c = tid + j * 128;
            int row = c >> 2, q = c & 3;
            CP16(smaddr(&As[buf][row][q * 8]), A + (size_t)(m0 + row) * DD + k0 + q * 8);
        }
        #pragma unroll
        for (int j = 0; j < 4; j++) {            // B: 512 x 16B chunks
            int c = tid + j * 128;
            int row = c >> 4, q = c & 15;
            CP16(smaddr(&Bs[buf][row][q * 8]), Bk + (size_t)(k0 + row) * DD + n0 + q * 8);
        }
    };

    load(0, 0); CPC();

    for (int it = 0; it < NIT; it++) {
        const int buf = it & 1;
        CPW0();
        __syncthreads();
        if (it + 1 < NIT) { load(it + 1, buf ^ 1); CPC(); }

        #pragma unroll
        for (int kd = 0; kd < 2; kd++) {
            const int kb = kd * 16;
            uint32_t a[4][4], bfr[4][4];
            #pragma unroll
            for (int mt = 0; mt < 4; mt++) {
                int mrow = wm0 + mt * 16 + tr + ((tile & 1) ? 8 : 0);
                int kcol = kb + ((tile >= 2) ? 8 : 0);
                ldsm_x4(a[mt], smaddr(&As[buf][mrow][kcol]));
            }
            #pragma unroll
            for (int p = 0; p < 4; p++) {
                int krow = kb + tr + ((tile & 1) ? 8 : 0);
                int ncol = wn0 + 16 * p + ((tile >= 2) ? 8 : 0);
                ldsm_x4_t(bfr[p], smaddr(&Bs[buf][krow][ncol]));
            }
            #pragma unroll
            for (int mt = 0; mt < 4; mt++)
                #pragma unroll
                for (int p = 0; p < 4; p++) {
                    mma_f16(acc[mt][2 * p],     a[mt], &bfr[p][0]);
                    mma_f16(acc[mt][2 * p + 1], a[mt], &bfr[p][2]);
                }
        }
    }

    if (dorope) {
        // RoPE in epilogue. Thread holds rows (m, m+8), cols (n, n+1), n even.
        __half* C = (__half*)Cp;
        const int base = (m0 + wm0 + grp) & (LL - 1);
        #pragma unroll
        for (int nt = 0; nt < 8; nt++) {
            const int n = n0 + wn0 + nt * 8 + 2 * tig;
            const int hc = (n & (DH - 1)) >> 1;
            float inv = exp2f(-(float)hc * 0.41524101186092029f);  // 10000^(-2hc/64)
            float sb, cb, s8, c8;
            sincosf((float)base * inv, &sb, &cb);
            sincosf(8.0f * inv, &s8, &c8);
            const float s16 = 2.f * s8 * c8;
            const float c16 = 1.f - 2.f * s8 * s8;
            float sl = sb, cl = cb;
            #pragma unroll
            for (int mt = 0; mt < 4; mt++) {
                const float sh = sl * c8 + cl * s8;
                const float ch = cl * c8 - sl * s8;
                const float x0 = acc[mt][nt][0] * scale, y0 = acc[mt][nt][1] * scale;
                const float x1 = acc[mt][nt][2] * scale, y1 = acc[mt][nt][3] * scale;
                const int m = m0 + wm0 + mt * 16 + grp;
                *(uint32_t*)(C + (size_t)m * DD + n) =
                    pack2(x0 * cl - y0 * sl, y0 * cl + x0 * sl);
                *(uint32_t*)(C + (size_t)(m + 8) * DD + n) =
                    pack2(x1 * ch - y1 * sh, y1 * ch + x1 * sh);
                const float sn = sl * c16 + cl * s16;
                const float cn = cl * c16 - sl * s16;
                sl = sn; cl = cn;
            }
        }
    } else {
        #pragma unroll
        for (int mt = 0; mt < 4; mt++) {
            #pragma unroll
            for (int nt = 0; nt < 8; nt++) {
                const int m = m0 + wm0 + mt * 16 + grp;
                const int n = n0 + wn0 + nt * 8 + 2 * tig;
                if (chalf) {
                    __half* C = (__half*)Cp;
                    *(uint32_t*)(C + (size_t)m * DD + n)       = pack2(acc[mt][nt][0] * scale, acc[mt][nt][1] * scale);
                    *(uint32_t*)(C + (size_t)(m + 8) * DD + n) = pack2(acc[mt][nt][2] * scale, acc[mt][nt][3] * scale);
                } else {
                    float* C = (float*)Cp;
                    *(float2*)(C + (size_t)m * DD + n) =
                        make_float2(acc[mt][nt][0] * scale, acc[mt][nt][1] * scale);
                    *(float2*)(C + (size_t)(m + 8) * DD + n) =
                        make_float2(acc[mt][nt][2] * scale, acc[mt][nt][3] * scale);
                }
            }
        }
    }
}

// q absorbs 1/sqrt(d) AND log2(e) so softmax runs in exp2 domain (rope is linear).
#define QSCALE 0.04508422002778011f   // log2(e) / 32

__global__ __launch_bounds__(128, 2) void gemm_qkv() {
    const __half* W = (blockIdx.z == 0) ? g_wq : (blockIdx.z == 1) ? g_wk : g_wv;
    __half* C       = (blockIdx.z == 0) ? g_q  : (blockIdx.z == 1) ? g_k  : g_v;
    float scale     = (blockIdx.z == 0) ? QSCALE : 1.0f;
    bool dorope     = (blockIdx.z != 2);
    gemm_body(g_x16, W, C, scale, true, dorope, blockIdx.y * BM, blockIdx.x * BN);
}

__global__ __launch_bounds__(128, 2) void gemm_out(float* __restrict__ out) {
    gemm_body(g_y, g_wo, out, 1.0f, false, false, blockIdx.y * BM, blockIdx.x * BN);
}

// ---------------------------------------------------------------------------
// fp16 tensor-core flash attention, 128-query CTAs (8 warps x 16 rows).
// exp2-domain softmax with packed ex2.approx.f16x2; row-sums via ones-MMA.
// ---------------------------------------------------------------------------
#define ONES2 0x3C003C00u   // half2(1.0, 1.0)

__global__ __launch_bounds__(256, 2) void flash_attn_f16() {
    __shared__ __half Ks[2][64][LDKh];   // [key j][d]
    __shared__ __half Vs[2][64][LDKh];   // [key j][d]

    const int qt  = (int)gridDim.x - 1 - blockIdx.x;   // heavy tiles first
    const int bh  = blockIdx.y;
    const int b   = bh >> 4;
    const int h   = bh & 15;
    const int tid = threadIdx.x;
    const int wid = tid >> 5;
    const int lane = tid & 31;
    const int grp = lane >> 2;
    const int tig = lane & 3;
    const int tile = lane >> 3;
    const int tr   = lane & 7;
    const int q0  = qt * 128;
    const int wrow = q0 + wid * 16;          // warp's first row
    const int row0 = wrow + grp;             // rows row0 and row0+8
    const int kt_max = (q0 + 127) >> 6;      // inclusive

    auto loadKV = [&](int kt, int buf) {
        const int kb = kt * 64;
        #pragma unroll
        for (int j = 0; j < 2; j++) {
            int c = tid + j * 256;
            int row = c >> 3, q = c & 7;
            size_t off = (size_t)(b * LL + kb + row) * DD + h * DH + q * 8;
            CP16(smaddr(&Ks[buf][row][q * 8]), g_k + off);
            CP16(smaddr(&Vs[buf][row][q * 8]), g_v + off);
        }
    };

    // Q fragments straight from gmem (fp16 pairs)
    uint32_t qa[4][4];
    {
        const __half* qr0 = g_q + ((size_t)(b * LL + row0)) * DD + h * DH;
        const __half* qr1 = qr0 + (size_t)8 * DD;
        #pragma unroll
        for (int kd = 0; kd < 4; kd++) {
            qa[kd][0] = *(const uint32_t*)(qr0 + kd * 16 + 2 * tig);
            qa[kd][1] = *(const uint32_t*)(qr1 + kd * 16 + 2 * tig);
            qa[kd][2] = *(const uint32_t*)(qr0 + kd * 16 + 2 * tig + 8);
            qa[kd][3] = *(const uint32_t*)(qr1 + kd * 16 + 2 * tig + 8);
        }
    }

    float o[8][4];
    #pragma unroll
    for (int dt = 0; dt < 8; dt++)
        #pragma unroll
        for (int r = 0; r < 4; r++) o[dt][r] = 0.f;
    float lacc[4] = {0.f, 0.f, 0.f, 0.f};    // row sums via ones-MMA ([0],[2] used)
    float m0 = -CUDART_INF_F, m1 = -CUDART_INF_F;

    loadKV(0, 0); CPC();

    for (int kt0 = 0; kt0 <= kt_max; kt0++) {
        const int kb = kt0 * 64;
        const int buf = kt0 & 1;
        CPW0();
        __syncthreads();
        if (kt0 < kt_max) { loadKV(kt0 + 1, buf ^ 1); CPC(); }

        if (kb <= wrow + 15) {
            // S = Q K^T  (logits already in log2 domain via QSCALE)
            float s[8][4];
            #pragma unroll
            for (int nt = 0; nt < 8; nt++)
                #pragma unroll
                for (int r = 0; r < 4; r++) s[nt][r] = 0.f;
            #pragma unroll
            for (int kd = 0; kd < 4; kd++) {
                uint32_t bfr[4][4];
                #pragma unroll
                for (int p = 0; p < 4; p++) {
                    int nrow = 16 * p + tr + ((tile >= 2) ? 8 : 0);
                    int kcol = kd * 16 + ((tile & 1) ? 8 : 0);
                    ldsm_x4(bfr[p], smaddr(&Ks[buf][nrow][kcol]));
                }
                #pragma unroll
                for (int p = 0; p < 4; p++) {
                    mma_f16(s[2 * p],     qa[kd], &bfr[p][0]);
                    mma_f16(s[2 * p + 1], qa[kd], &bfr[p][2]);
                }
            }

            // causal mask (tiles overlapping this warp's diagonal)
            if (kb + 63 > wrow) {
                #pragma unroll
                for (int nt = 0; nt < 8; nt++) {
                    const int j = kb + nt * 8 + 2 * tig;
                    if (j     > row0)     s[nt][0] = -CUDART_INF_F;
                    if (j + 1 > row0)     s[nt][1] = -CUDART_INF_F;
                    if (j     > row0 + 8) s[nt][2] = -CUDART_INF_F;
                    if (j + 1 > row0 + 8) s[nt][3] = -CUDART_INF_F;
                }
            }

            // online softmax (exp2 domain)
            float t0 = s[0][0], t1 = s[0][2];
            #pragma unroll
            for (int nt = 0; nt < 8; nt++) {
                t0 = fmaxf(t0, fmaxf(s[nt][0], s[nt][1]));
                t1 = fmaxf(t1, fmaxf(s[nt][2], s[nt][3]));
            }
            t0 = fmaxf(t0, __shfl_xor_sync(0xffffffffu, t0, 1));
            t0 = fmaxf(t0, __shfl_xor_sync(0xffffffffu, t0, 2));
            t1 = fmaxf(t1, __shfl_xor_sync(0xffffffffu, t1, 1));
            t1 = fmaxf(t1, __shfl_xor_sync(0xffffffffu, t1, 2));
            const float mn0 = fmaxf(m0, t0), mn1 = fmaxf(m1, t1);
            const float c0 = exp2a(m0 - mn0), c1 = exp2a(m1 - mn1);
            m0 = mn0; m1 = mn1;
            lacc[0] *= c0; lacc[2] *= c1;
            #pragma unroll
            for (int dt = 0; dt < 8; dt++) {
                o[dt][0] *= c0; o[dt][1] *= c0;
                o[dt][2] *= c1; o[dt][3] *= c1;
            }

            // O += P V ; l += P @ ones. P = exp2(s - m) computed directly in
            // packed fp16 (ex2.approx.f16x2) — the result IS the MMA A-fragment.
            #pragma unroll
            for (int kk2 = 0; kk2 < 4; kk2++) {
                uint32_t pa[4] = {
                    exp2h2(s[2 * kk2][0] - m0,     s[2 * kk2][1] - m0),
                    exp2h2(s[2 * kk2][2] - m1,     s[2 * kk2][3] - m1),
                    exp2h2(s[2 * kk2 + 1][0] - m0, s[2 * kk2 + 1][1] - m0),
                    exp2h2(s[2 * kk2 + 1][2] - m1, s[2 * kk2 + 1][3] - m1) };
                uint32_t onesb[2] = { ONES2, ONES2 };
                mma_f16(lacc, pa, onesb);
                uint32_t bfr[4][4];
                #pragma unroll
                for (int p = 0; p < 4; p++) {
                    int jrow = kk2 * 16 + tr + ((tile & 1) ? 8 : 0);
                    int dcol = 16 * p + ((tile >= 2) ? 8 : 0);
                    ldsm_x4_t(bfr[p], smaddr(&Vs[buf][jrow][dcol]));
                }
                #pragma unroll
                for (int p = 0; p < 4; p++) {
                    mma_f16(o[2 * p],     pa, &bfr[p][0]);
                    mma_f16(o[2 * p + 1], pa, &bfr[p][2]);
                }
            }
        }
    }

    // final normalize + store (fp16); lacc holds full row sums (no reduce needed)
    const float i0 = 1.f / lacc[0], i1 = 1.f / lacc[2];
    __half* y0 = g_y + ((size_t)(b * LL + row0)) * DD + h * DH;
    __half* y1 = y0 + (size_t)8 * DD;
    #pragma unroll
    for (int dt = 0; dt < 8; dt++) {
        *(uint32_t*)(y0 + dt * 8 + 2 * tig) = pack2(o[dt][0] * i0, o[dt][1] * i0);
        *(uint32_t*)(y1 + dt * 8 + 2 * tig) = pack2(o[dt][2] * i1, o[dt][3] * i1);
    }
}

// ---------------------------------------------------------------------------
extern "C" void kernel_launch(void* const* d_in, const int* in_sizes, int n_in,
                              void* d_out, int out_size) {
    const float* x  = (const float*)d_in[0];
    const float* Wq = (const float*)d_in[1];
    const float* Wk = (const float*)d_in[2];
    const float* Wv = (const float*)d_in[3];
    const float* Wo = (const float*)d_in[4];
    float* out = (float*)d_out;

    const int ntot = NX4 + 4 * NW4;
    cvt_all<<<(ntot + 255) / 256, 256>>>(x, Wq, Wk, Wv, Wo);

    dim3 qkvgrid(DD / BN, MM / BM, 3);   // (8, 32, 3)
    gemm_qkv<<<qkvgrid, 128>>>();

    dim3 agrid(16, BB * HH);
    flash_attn_f16<<<agrid, 256>>>();

    dim3 ggrid(DD / BN, MM / BM);        // (8, 32)
    gemm_out<<<ggrid, 128>>>(out);
}